// round 9
// baseline (speedup 1.0000x reference)
#include <cuda_runtime.h>
#include <cuda_bf16.h>
#include <cuda_fp16.h>

#define NSP 4096
#define CDIM 256
#define NB 8
#define BQ 64
#define BK 64
#define NK (NSP / BK)
#define LOG2E 1.4426950408889634f

// ---- scratch ----
__device__ __align__(256) __half g_Qh1[(size_t)NB * NSP * CDIM];  // [b][n][c] hi (xLOG2E)
__device__ __align__(256) __half g_Qh2[(size_t)NB * NSP * CDIM];  // [b][n][c] lo
__device__ __align__(256) __half g_Kh [(size_t)NB * NSP * CDIM];  // [b][n][c] fp16
__device__ __align__(256) float  g_V  [(size_t)NB * CDIM * NSP];  // [b][c][n] tf32
__device__ __align__(256) __nv_bfloat16 g_Xx1[(size_t)NB * NSP * CDIM];
__device__ __align__(256) __nv_bfloat16 g_Xx2[(size_t)NB * NSP * CDIM];
__device__ __align__(256) __nv_bfloat16 g_Xa1[(size_t)NB * NSP * CDIM];
__device__ __align__(256) __nv_bfloat16 g_Xa2[(size_t)NB * NSP * CDIM];
__device__ __align__(256) __nv_bfloat16 g_W1[3][65536];
__device__ __align__(256) __nv_bfloat16 g_W2[3][65536];

typedef unsigned long long u64;
typedef unsigned int u32;
typedef unsigned short u16;

// ================= helpers =================
__device__ __forceinline__ u32 smem_u32(const void* p) {
    u32 a;
    asm("{ .reg .u64 t; cvta.to.shared.u64 t, %1; cvt.u32.u64 %0, t; }" : "=r"(a) : "l"(p));
    return a;
}
__device__ __forceinline__ float tf32r(float f) {
    float o; asm("cvt.rna.tf32.f32 %0, %1;" : "=f"(o) : "f"(f)); return o;
}
__device__ __forceinline__ float ex2f(float x) {
    float y; asm("ex2.approx.f32 %0, %1;" : "=f"(y) : "f"(x)); return y;
}
__device__ __forceinline__ void ldsm4(u32* r, u32 addr) {
    asm volatile("ldmatrix.sync.aligned.m8n8.x4.shared.b16 {%0,%1,%2,%3}, [%4];"
                 : "=r"(r[0]), "=r"(r[1]), "=r"(r[2]), "=r"(r[3]) : "r"(addr));
}
__device__ __forceinline__ void mma_bf16(float* d, const u32* a, u32 b0, u32 b1) {
    asm volatile(
        "mma.sync.aligned.m16n8k16.row.col.f32.bf16.bf16.f32 "
        "{%0,%1,%2,%3}, {%4,%5,%6,%7}, {%8,%9}, {%0,%1,%2,%3};"
        : "+f"(d[0]), "+f"(d[1]), "+f"(d[2]), "+f"(d[3])
        : "r"(a[0]), "r"(a[1]), "r"(a[2]), "r"(a[3]), "r"(b0), "r"(b1));
}
__device__ __forceinline__ void mma_f16(float* d, const u32* a, u32 b0, u32 b1) {
    asm volatile(
        "mma.sync.aligned.m16n8k16.row.col.f32.f16.f16.f32 "
        "{%0,%1,%2,%3}, {%4,%5,%6,%7}, {%8,%9}, {%0,%1,%2,%3};"
        : "+f"(d[0]), "+f"(d[1]), "+f"(d[2]), "+f"(d[3])
        : "r"(a[0]), "r"(a[1]), "r"(a[2]), "r"(a[3]), "r"(b0), "r"(b1));
}
__device__ __forceinline__ void mma_tf32(float* d, u32 a0, u32 a1, u32 a2, u32 a3,
                                         u32 b0, u32 b1) {
    asm volatile(
        "mma.sync.aligned.m16n8k8.row.col.f32.tf32.tf32.f32 "
        "{%0,%1,%2,%3}, {%4,%5,%6,%7}, {%8,%9}, {%0,%1,%2,%3};"
        : "+f"(d[0]), "+f"(d[1]), "+f"(d[2]), "+f"(d[3])
        : "r"(a0), "r"(a1), "r"(a2), "r"(a3), "r"(b0), "r"(b1));
}
__device__ __forceinline__ u32 lds_u32(u32 a) {
    u32 v; asm volatile("ld.shared.b32 %0, [%1];" : "=r"(v) : "r"(a)); return v;
}
__device__ __forceinline__ float lds_f32(u32 a) {
    float v; asm volatile("ld.shared.f32 %0, [%1];" : "=f"(v) : "r"(a)); return v;
}
__device__ __forceinline__ void sts_v2f(u32 a, float x, float y) {
    asm volatile("st.shared.v2.f32 [%0], {%1,%2};" :: "r"(a), "f"(x), "f"(y) : "memory");
}
__device__ __forceinline__ void sts_v4(u32 a, uint4 v) {
    asm volatile("st.shared.v4.b32 [%0], {%1,%2,%3,%4};"
                 :: "r"(a), "r"(v.x), "r"(v.y), "r"(v.z), "r"(v.w) : "memory");
}
#define CP16(dst, src) asm volatile("cp.async.cg.shared.global [%0], [%1], 16;" \
    :: "r"(dst), "l"(src) : "memory")
#define CPCOMMIT() asm volatile("cp.async.commit_group;" ::: "memory")
#define CPWAIT(n)  asm volatile("cp.async.wait_group %0;" :: "n"(n) : "memory")
#define BAR_GRP(id) asm volatile("bar.sync %0, %1;" :: "r"(id), "r"(128) : "memory")

__device__ __forceinline__ void bfsplit(float f, u16& hi, u16& lo) {
    __nv_bfloat16 h = __float2bfloat16_rn(f);
    __nv_bfloat16 l = __float2bfloat16_rn(f - __bfloat162float(h));
    hi = __bfloat16_as_ushort(h);
    lo = __bfloat16_as_ushort(l);
}

// ---------------------------------------------------------------------------
// Kernel A: split weights into bf16 hi/lo pairs.
// ---------------------------------------------------------------------------
__global__ __launch_bounds__(256) void split_w(
    const float* __restrict__ Wq, const float* __restrict__ Wk,
    const float* __restrict__ Wv)
{
    int idx = blockIdx.x * 256 + threadIdx.x;
    int which = idx >> 16;
    int i = idx & 65535;
    const float* W = (which == 0) ? Wq : (which == 1) ? Wk : Wv;
    u16 h, l;
    bfsplit(W[i], h, l);
    g_W1[which][i] = __ushort_as_bfloat16(h);
    g_W2[which][i] = __ushort_as_bfloat16(l);
}

// ---------------------------------------------------------------------------
// Kernel B: split + transpose x/attr -> [b][n][c] bf16 hi/lo.
// ---------------------------------------------------------------------------
__global__ __launch_bounds__(256) void split_x(
    const float* __restrict__ x, const float* __restrict__ attr)
{
    __shared__ float t[32][33];
    const int tid = threadIdx.x;
    const int b = blockIdx.z >> 1, ten = blockIdx.z & 1;
    const float* src = ten ? attr : x;
    __nv_bfloat16* d1 = ten ? g_Xa1 : g_Xx1;
    __nv_bfloat16* d2 = ten ? g_Xa2 : g_Xx2;
    const int n0 = blockIdx.x * 32, c0 = blockIdx.y * 32;

    {
        int r = tid >> 3, n4 = (tid & 7) * 4;
        float4 v = *(const float4*)(src + ((size_t)b * CDIM + c0 + r) * NSP + n0 + n4);
        t[r][n4 + 0] = v.x; t[r][n4 + 1] = v.y;
        t[r][n4 + 2] = v.z; t[r][n4 + 3] = v.w;
    }
    __syncthreads();
    {
        int nr = tid >> 3, c4 = (tid & 7) * 4;
        u16 h[4], l[4];
        #pragma unroll
        for (int k = 0; k < 4; k++) bfsplit(t[c4 + k][nr], h[k], l[k]);
        uint2 hw, lw;
        hw.x = (u32)h[0] | ((u32)h[1] << 16); hw.y = (u32)h[2] | ((u32)h[3] << 16);
        lw.x = (u32)l[0] | ((u32)l[1] << 16); lw.y = (u32)l[2] | ((u32)l[3] << 16);
        size_t base = ((size_t)b * NSP + n0 + nr) * CDIM + c0 + c4;
        *(uint2*)&d1[base] = hw;
        *(uint2*)&d2[base] = lw;
    }
}

// ---------------------------------------------------------------------------
// Kernel C: proj via mma (3-pass split bf16 core).  (unchanged from R8)
// ---------------------------------------------------------------------------
#define PJ_X1 0
#define PJ_X2 33792
#define PJ_W  67584
#define PJ_ST 202752
#define PJ_B  220160
#define PJ_TOTAL 221184

__global__ __launch_bounds__(256, 1) void proj_mma(
    const float* __restrict__ bq, const float* __restrict__ bk,
    const float* __restrict__ bv)
{
    extern __shared__ __align__(16) char smem[];
    const u32 sb = smem_u32(smem);
    const int tid = threadIdx.x;
    const int lane = tid & 31, warp = tid >> 5;
    const int wr = warp >> 1, wc = warp & 1;
    const int gid = lane >> 2, tig = lane & 3;
    const int z = blockIdx.z, bb = blockIdx.y, n0 = blockIdx.x * 64;

    const __nv_bfloat16* xs1 = (z == 0) ? g_Xx1 : g_Xa1;
    const __nv_bfloat16* xs2 = (z == 0) ? g_Xx2 : g_Xa2;
    const __nv_bfloat16* w1 = g_W1[z];
    const __nv_bfloat16* w2 = g_W2[z];
    const float* bias = (z == 0) ? bq : (z == 1) ? bk : bv;

    float* bias_s = (float*)(smem + PJ_B);
    bias_s[tid] = bias[tid];

    #pragma unroll
    for (int it = 0; it < 8; it++) {
        int idx = it * 256 + tid;
        int j = idx >> 5, ch = idx & 31;
        size_t off = ((size_t)bb * NSP + n0 + j) * CDIM + ch * 8;
        CP16(sb + PJ_X1 + j * 528 + ch * 16, xs1 + off);
        CP16(sb + PJ_X2 + j * 528 + ch * 16, xs2 + off);
    }
    CPCOMMIT();

    auto issueW = [&](int oq) {
        u32 base = sb + PJ_W + (oq & 1) * 67584;
        #pragma unroll
        for (int it = 0; it < 8; it++) {
            int idx = it * 256 + tid;
            int o = idx >> 5, ch = idx & 31;
            size_t off = (size_t)(oq * 64 + o) * CDIM + ch * 8;
            CP16(base + o * 528 + ch * 16, w1 + off);
            CP16(base + 33792 + o * 528 + ch * 16, w2 + off);
        }
        CPCOMMIT();
    };
    issueW(0);

    const u32 aB1 = sb + PJ_X1 + (wr * 16 + (lane & 15)) * 528 + (lane >> 4) * 16;
    const u32 aB2 = sb + PJ_X2 + (wr * 16 + (lane & 15)) * 528 + (lane >> 4) * 16;
    const int bRow = wc * 32 + (lane & 7) + ((lane >> 4) << 3);
    const u32 bOffc = ((lane >> 3) & 1) * 16;

    for (int oq = 0; oq < 4; oq++) {
        CPWAIT(0);
        __syncthreads();
        if (oq < 3) issueW(oq + 1);

        u32 wbase = sb + PJ_W + (oq & 1) * 67584;
        u32 bB1 = wbase + bRow * 528 + bOffc;
        u32 bB2 = bB1 + 33792;

        float D[4][4];
        #pragma unroll
        for (int t = 0; t < 4; t++)
            #pragma unroll
            for (int e = 0; e < 4; e++) D[t][e] = 0.0f;

        #pragma unroll
        for (int kk = 0; kk < 16; kk++) {
            u32 a1[4], a2[4], bw1[8], bw2[8];
            ldsm4(a1, aB1 + kk * 32);
            ldsm4(a2, aB2 + kk * 32);
            ldsm4(bw1,     bB1 + kk * 32);
            ldsm4(bw1 + 4, bB1 + 16 * 528 + kk * 32);
            ldsm4(bw2,     bB2 + kk * 32);
            ldsm4(bw2 + 4, bB2 + 16 * 528 + kk * 32);
            #pragma unroll
            for (int t = 0; t < 4; t++) {
                mma_bf16(D[t], a1, bw1[2 * t], bw1[2 * t + 1]);
                mma_bf16(D[t], a1, bw2[2 * t], bw2[2 * t + 1]);
                mma_bf16(D[t], a2, bw1[2 * t], bw1[2 * t + 1]);
            }
        }

        if (z < 2) {
            #pragma unroll
            for (int t = 0; t < 4; t++) {
                int o = oq * 64 + wc * 32 + t * 8 + 2 * tig;
                float b0 = bias_s[o], b1 = bias_s[o + 1];
                #pragma unroll
                for (int rh = 0; rh < 2; rh++) {
                    float f0 = D[t][2 * rh + 0] + b0;
                    float f1 = D[t][2 * rh + 1] + b1;
                    int n = n0 + wr * 16 + gid + rh * 8;
                    size_t idx = ((size_t)bb * NSP + n) * CDIM + o;
                    if (z == 0) {
                        f0 *= LOG2E; f1 *= LOG2E;
                        __half h0 = __float2half_rn(f0);
                        __half h1 = __float2half_rn(f1);
                        __half l0 = __float2half_rn(f0 - __half2float(h0));
                        __half l1 = __float2half_rn(f1 - __half2float(h1));
                        *(u32*)&g_Qh1[idx] =
                            (u32)__half_as_ushort(h0) | ((u32)__half_as_ushort(h1) << 16);
                        *(u32*)&g_Qh2[idx] =
                            (u32)__half_as_ushort(l0) | ((u32)__half_as_ushort(l1) << 16);
                    } else {
                        __half h0 = __float2half_rn(f0);
                        __half h1 = __float2half_rn(f1);
                        *(u32*)&g_Kh[idx] =
                            (u32)__half_as_ushort(h0) | ((u32)__half_as_ushort(h1) << 16);
                    }
                }
            }
        } else {
            float* st = (float*)(smem + PJ_ST);
            #pragma unroll
            for (int t = 0; t < 4; t++) {
                int ol = wc * 32 + t * 8 + 2 * tig;
                float b0 = bias_s[oq * 64 + ol], b1 = bias_s[oq * 64 + ol + 1];
                #pragma unroll
                for (int rh = 0; rh < 2; rh++) {
                    int nl = wr * 16 + gid + rh * 8;
                    st[ol * 68 + nl]       = D[t][2 * rh + 0] + b0;
                    st[(ol + 1) * 68 + nl] = D[t][2 * rh + 1] + b1;
                }
            }
            __syncthreads();
            int ol = tid >> 2, nch = (tid & 3) * 16;
            float* dst = g_V + ((size_t)bb * CDIM + oq * 64 + ol) * NSP + n0 + nch;
            #pragma unroll
            for (int k = 0; k < 4; k++) {
                float4 v;
                v.x = tf32r(st[ol * 68 + nch + 4 * k + 0]);
                v.y = tf32r(st[ol * 68 + nch + 4 * k + 1]);
                v.z = tf32r(st[ol * 68 + nch + 4 * k + 2]);
                v.w = tf32r(st[ol * 68 + nch + 4 * k + 3]);
                *(float4*)(dst + 4 * k) = v;
            }
        }
    }
}

// ---------------------------------------------------------------------------
// Kernel D: flash attention, 512 threads (16 warps: wr=warp&3 i-slice,
// wc=warp>>2 j/c-quarter).  fp16 2-pass QK, tf32 PV, max-free softmax.
// ---------------------------------------------------------------------------
#define SQ1 0
#define SQ2 33792
#define SK  67584
#define SV  101376
#define SP  171008
#define SLR 188416
#define SM_TOTAL 188672
#define QK_STR 528
#define VP_STR 272
#define OT_STR 258

__global__ __launch_bounds__(512, 1) void attn_kernel(
    const float* __restrict__ x, float* __restrict__ out)
{
    extern __shared__ __align__(16) char smem[];
    const u32 sb = smem_u32(smem);
    const int tid = threadIdx.x;
    const int lane = tid & 31;
    const int warp = tid >> 5;          // 0..15
    const int wr = warp & 3;            // i-slice (16 rows)
    const int wc = warp >> 2;           // 0..3 : j-quarter (S) / c-quarter (PV)
    const int gid = lane >> 2, tig = lane & 3;
    const int i0 = wr * 16;
    const int j0 = wc * 16;
    const int c0 = wc * 64;
    const int bb = blockIdx.y;
    const int n0 = blockIdx.x * BQ;

    float* lrow = (float*)(smem + SLR);
    if (tid < 64) lrow[tid] = 0.0f;

    const __half* q1g = g_Qh1 + ((size_t)bb * NSP + n0) * CDIM;
    const __half* q2g = g_Qh2 + ((size_t)bb * NSP + n0) * CDIM;
    const __half* khg = g_Kh  + (size_t)bb * NSP * CDIM;
    const float*  vg  = g_V   + (size_t)bb * CDIM * NSP;

    // ---- Q tiles (both fp16 splits): 64 rows x 512B each ----
    #pragma unroll
    for (int it = 0; it < 4; it++) {
        int idx = it * 512 + tid;
        int i = idx >> 5, ch = idx & 31;
        uint4 v1 = *(const uint4*)&q1g[(size_t)i * CDIM + ch * 8];
        uint4 v2 = *(const uint4*)&q2g[(size_t)i * CDIM + ch * 8];
        sts_v4(sb + SQ1 + i * QK_STR + ch * 16, v1);
        sts_v4(sb + SQ2 + i * QK_STR + ch * 16, v2);
    }

    auto issueK = [&](int k0) {
        #pragma unroll
        for (int it = 0; it < 4; it++) {
            int idx = it * 512 + tid;
            int j = idx >> 5, ch = idx & 31;
            CP16(sb + SK + j * QK_STR + ch * 16, &khg[(size_t)(k0 + j) * CDIM + ch * 8]);
        }
        CPCOMMIT();
    };
    auto issueV = [&](int k0) {
        #pragma unroll
        for (int it = 0; it < 8; it++) {
            int idx = it * 512 + tid;
            int c = idx >> 4, ch = idx & 15;
            CP16(sb + SV + c * VP_STR + ch * 16, &vg[(size_t)c * NSP + k0 + ch * 4]);
        }
        CPCOMMIT();
    };

    issueK(0);
    issueV(0);

    const u32 aBase1 = sb + SQ1 + (i0 + (lane & 15)) * QK_STR + (lane >> 4) * 16;
    const u32 aBase2 = sb + SQ2 + (i0 + (lane & 15)) * QK_STR + (lane >> 4) * 16;
    const int bRow = j0 + (lane & 7) + ((lane >> 4) << 3);
    const u32 bOff = ((lane >> 3) & 1) * 16;
    const u32 bBase = sb + SK + bRow * QK_STR + bOff;

    float O[8][4];
    #pragma unroll
    for (int t = 0; t < 8; t++)
        #pragma unroll
        for (int e = 0; e < 4; e++) O[t][e] = 0.0f;
    float lsum0 = 0.0f, lsum1 = 0.0f;

    for (int kt = 0; kt < NK; kt++) {
        CPWAIT(1);                  // K(kt) ready
        __syncthreads();

        // ---- S = (q1+q2) * k : 16i x 16j per warp, fp16 2-pass ----
        float S[2][4];
        #pragma unroll
        for (int t = 0; t < 2; t++)
            #pragma unroll
            for (int e = 0; e < 4; e++) S[t][e] = 0.0f;

        #pragma unroll
        for (int kk = 0; kk < 16; kk++) {
            u32 aq1[4], aq2[4], bk[4];
            ldsm4(aq1, aBase1 + kk * 32);
            ldsm4(aq2, aBase2 + kk * 32);
            ldsm4(bk, bBase + kk * 32);
            #pragma unroll
            for (int t = 0; t < 2; t++) {
                mma_f16(S[t], aq1, bk[2 * t], bk[2 * t + 1]);
                mma_f16(S[t], aq2, bk[2 * t], bk[2 * t + 1]);
            }
        }

        CPWAIT(0);                  // V(kt) ready; K fully read
        __syncthreads();
        issueK(((kt + 1) & (NK - 1)) * BK);

        // ---- P = exp2(S) (max-free), tf32 to smem ----
        #pragma unroll
        for (int t = 0; t < 2; t++) {
            int jc = j0 + 8 * t + 2 * tig;
            float p0 = ex2f(S[t][0]), p1 = ex2f(S[t][1]);
            float p2 = ex2f(S[t][2]), p3 = ex2f(S[t][3]);
            lsum0 += p0 + p1;
            lsum1 += p2 + p3;
            sts_v2f(sb + SP + ((i0 + gid) * 68 + jc) * 4, tf32r(p0), tf32r(p1));
            sts_v2f(sb + SP + ((i0 + gid + 8) * 68 + jc) * 4, tf32r(p2), tf32r(p3));
        }
        BAR_GRP(1 + wr);            // 4 wc-warps of this i-slice exchange P

        // ---- O += P @ V^T : 16i x 64c per warp, tf32, k=64 ----
        const u32 pB = sb + SP + ((i0 + gid) * 68 + tig) * 4;
        const u32 vB = sb + SV + ((c0 + gid) * 68 + tig) * 4;
        #pragma unroll
        for (int ks = 0; ks < 8; ks++) {
            u32 pa = pB + ks * 32;
            u32 a0 = lds_u32(pa);
            u32 a1 = lds_u32(pa + 8 * VP_STR);
            u32 a2 = lds_u32(pa + 16);
            u32 a3 = lds_u32(pa + 8 * VP_STR + 16);
            #pragma unroll
            for (int t = 0; t < 8; t++) {
                u32 vb = vB + t * 8 * VP_STR + ks * 32;
                u32 b0 = lds_u32(vb);
                u32 b1 = lds_u32(vb + 16);
                mma_tf32(O[t], a0, a1, a2, a3, b0, b1);
            }
        }
        __syncthreads();            // V (and P) fully read
        if (kt + 1 < NK) issueV((kt + 1) * BK);
    }

    CPWAIT(0);

    // ---- per-row l: quad reduce + atomic over 4 wc warps ----
    lsum0 += __shfl_xor_sync(0xffffffffu, lsum0, 1);
    lsum0 += __shfl_xor_sync(0xffffffffu, lsum0, 2);
    lsum1 += __shfl_xor_sync(0xffffffffu, lsum1, 1);
    lsum1 += __shfl_xor_sync(0xffffffffu, lsum1, 2);
    if (tig == 0) {
        atomicAdd(&lrow[i0 + gid], lsum0);
        atomicAdd(&lrow[i0 + gid + 8], lsum1);
    }
    __syncthreads();

    // ---- transpose O through smem (reuse V region) ----
    #pragma unroll
    for (int t = 0; t < 8; t++) {
        int c = c0 + 8 * t + 2 * tig;
        sts_v2f(sb + SV + ((i0 + gid) * OT_STR + c) * 4, O[t][0], O[t][1]);
        sts_v2f(sb + SV + ((i0 + gid + 8) * OT_STR + c) * 4, O[t][2], O[t][3]);
    }
    __syncthreads();

    // ---- out = O/l + x, coalesced ----
    const float* xb = x + (size_t)bb * CDIM * NSP;
    float* ob = out + (size_t)bb * CDIM * NSP;
    const int i = tid & 63;
    const int cg = tid >> 6;            // 0..7
    const float invl = 1.0f / lrow[i];
    #pragma unroll 4
    for (int cc = 0; cc < 32; cc++) {
        int c = cc * 8 + cg;
        float ov = lds_f32(sb + SV + (i * OT_STR + c) * 4);
        size_t g = (size_t)c * NSP + n0 + i;
        ob[g] = ov * invl + xb[g];
    }
}

// ---------------------------------------------------------------------------
extern "C" void kernel_launch(void* const* d_in, const int* in_sizes, int n_in,
                              void* d_out, int out_size)
{
    const float* x    = (const float*)d_in[0];
    const float* attr = (const float*)d_in[1];
    const float* Wq   = (const float*)d_in[2];
    const float* bq   = (const float*)d_in[3];
    const float* Wk   = (const float*)d_in[4];
    const float* bk   = (const float*)d_in[5];
    const float* Wv   = (const float*)d_in[6];
    const float* bv   = (const float*)d_in[7];
    float* out = (float*)d_out;

    cudaFuncSetAttribute(proj_mma,
                         cudaFuncAttributeMaxDynamicSharedMemorySize, PJ_TOTAL);
    cudaFuncSetAttribute(attn_kernel,
                         cudaFuncAttributeMaxDynamicSharedMemorySize, SM_TOTAL);

    split_w<<<768, 256>>>(Wq, Wk, Wv);
    split_x<<<dim3(NSP / 32, CDIM / 32, NB * 2), 256>>>(x, attr);
    proj_mma<<<dim3(NSP / 64, NB, 3), 256, PJ_TOTAL>>>(bq, bk, bv);
    attn_kernel<<<dim3(NSP / BQ, NB), 512, SM_TOTAL>>>(x, out);
}

// round 10
// speedup vs baseline: 1.4033x; 1.4033x over previous
#include <cuda_runtime.h>
#include <cuda_bf16.h>
#include <cuda_fp16.h>

#define NSP 4096
#define CDIM 256
#define NB 8
#define BQ 64
#define BK 64
#define NK (NSP / BK)
#define LOG2E 1.4426950408889634f

// ---- scratch ----
__device__ __align__(256) __half g_Qh[(size_t)NB * NSP * CDIM];   // [b][n][c] fp16 (xLOG2E)
__device__ __align__(256) __half g_Kh[(size_t)NB * NSP * CDIM];   // [b][n][c] fp16
__device__ __align__(256) __half g_Vh[(size_t)NB * CDIM * NSP];   // [b][c][n'] fp16, j-perm
__device__ __align__(256) __nv_bfloat16 g_Xx1[(size_t)NB * NSP * CDIM];
__device__ __align__(256) __nv_bfloat16 g_Xx2[(size_t)NB * NSP * CDIM];
__device__ __align__(256) __nv_bfloat16 g_Xa1[(size_t)NB * NSP * CDIM];
__device__ __align__(256) __nv_bfloat16 g_Xa2[(size_t)NB * NSP * CDIM];
__device__ __align__(256) __nv_bfloat16 g_W1[3][65536];
__device__ __align__(256) __nv_bfloat16 g_W2[3][65536];

typedef unsigned long long u64;
typedef unsigned int u32;
typedef unsigned short u16;

// ================= helpers =================
__device__ __forceinline__ u32 smem_u32(const void* p) {
    u32 a;
    asm("{ .reg .u64 t; cvta.to.shared.u64 t, %1; cvt.u32.u64 %0, t; }" : "=r"(a) : "l"(p));
    return a;
}
__device__ __forceinline__ float tf32r(float f) {
    float o; asm("cvt.rna.tf32.f32 %0, %1;" : "=f"(o) : "f"(f)); return o;
}
__device__ __forceinline__ float ex2f(float x) {
    float y; asm("ex2.approx.f32 %0, %1;" : "=f"(y) : "f"(x)); return y;
}
__device__ __forceinline__ void ldsm4(u32* r, u32 addr) {
    asm volatile("ldmatrix.sync.aligned.m8n8.x4.shared.b16 {%0,%1,%2,%3}, [%4];"
                 : "=r"(r[0]), "=r"(r[1]), "=r"(r[2]), "=r"(r[3]) : "r"(addr));
}
__device__ __forceinline__ void mma_bf16(float* d, const u32* a, u32 b0, u32 b1) {
    asm volatile(
        "mma.sync.aligned.m16n8k16.row.col.f32.bf16.bf16.f32 "
        "{%0,%1,%2,%3}, {%4,%5,%6,%7}, {%8,%9}, {%0,%1,%2,%3};"
        : "+f"(d[0]), "+f"(d[1]), "+f"(d[2]), "+f"(d[3])
        : "r"(a[0]), "r"(a[1]), "r"(a[2]), "r"(a[3]), "r"(b0), "r"(b1));
}
__device__ __forceinline__ void mma_f16(float* d, const u32* a, u32 b0, u32 b1) {
    asm volatile(
        "mma.sync.aligned.m16n8k16.row.col.f32.f16.f16.f32 "
        "{%0,%1,%2,%3}, {%4,%5,%6,%7}, {%8,%9}, {%0,%1,%2,%3};"
        : "+f"(d[0]), "+f"(d[1]), "+f"(d[2]), "+f"(d[3])
        : "r"(a[0]), "r"(a[1]), "r"(a[2]), "r"(a[3]), "r"(b0), "r"(b1));
}
__device__ __forceinline__ void mma_tf32(float* d, u32 a0, u32 a1, u32 a2, u32 a3,
                                         u32 b0, u32 b1) {
    asm volatile(
        "mma.sync.aligned.m16n8k8.row.col.f32.tf32.tf32.f32 "
        "{%0,%1,%2,%3}, {%4,%5,%6,%7}, {%8,%9}, {%0,%1,%2,%3};"
        : "+f"(d[0]), "+f"(d[1]), "+f"(d[2]), "+f"(d[3])
        : "r"(a0), "r"(a1), "r"(a2), "r"(a3), "r"(b0), "r"(b1));
}
__device__ __forceinline__ u32 lds_u32(u32 a) {
    u32 v; asm volatile("ld.shared.b32 %0, [%1];" : "=r"(v) : "r"(a)); return v;
}
__device__ __forceinline__ float lds_f32(u32 a) {
    float v; asm volatile("ld.shared.f32 %0, [%1];" : "=f"(v) : "r"(a)); return v;
}
__device__ __forceinline__ void sts_v2f(u32 a, float x, float y) {
    asm volatile("st.shared.v2.f32 [%0], {%1,%2};" :: "r"(a), "f"(x), "f"(y) : "memory");
}
__device__ __forceinline__ void sts_v4(u32 a, uint4 v) {
    asm volatile("st.shared.v4.b32 [%0], {%1,%2,%3,%4};"
                 :: "r"(a), "r"(v.x), "r"(v.y), "r"(v.z), "r"(v.w) : "memory");
}
#define CP16(dst, src) asm volatile("cp.async.cg.shared.global [%0], [%1], 16;" \
    :: "r"(dst), "l"(src) : "memory")
#define CPCOMMIT() asm volatile("cp.async.commit_group;" ::: "memory")
#define CPWAIT(n)  asm volatile("cp.async.wait_group %0;" :: "n"(n) : "memory")
#define BAR_GRP(id) asm volatile("bar.sync %0, %1;" :: "r"(id), "r"(128) : "memory")

__device__ __forceinline__ void bfsplit(float f, u16& hi, u16& lo) {
    __nv_bfloat16 h = __float2bfloat16_rn(f);
    __nv_bfloat16 l = __float2bfloat16_rn(f - __bfloat162float(h));
    hi = __bfloat16_as_ushort(h);
    lo = __bfloat16_as_ushort(l);
}

// ---------------------------------------------------------------------------
// Kernel A: split weights into bf16 hi/lo pairs.
// ---------------------------------------------------------------------------
__global__ __launch_bounds__(256) void split_w(
    const float* __restrict__ Wq, const float* __restrict__ Wk,
    const float* __restrict__ Wv)
{
    int idx = blockIdx.x * 256 + threadIdx.x;
    int which = idx >> 16;
    int i = idx & 65535;
    const float* W = (which == 0) ? Wq : (which == 1) ? Wk : Wv;
    u16 h, l;
    bfsplit(W[i], h, l);
    g_W1[which][i] = __ushort_as_bfloat16(h);
    g_W2[which][i] = __ushort_as_bfloat16(l);
}

// ---------------------------------------------------------------------------
// Kernel B: split + transpose x/attr -> [b][n][c] bf16 hi/lo.
// ---------------------------------------------------------------------------
__global__ __launch_bounds__(256) void split_x(
    const float* __restrict__ x, const float* __restrict__ attr)
{
    __shared__ float t[32][33];
    const int tid = threadIdx.x;
    const int b = blockIdx.z >> 1, ten = blockIdx.z & 1;
    const float* src = ten ? attr : x;
    __nv_bfloat16* d1 = ten ? g_Xa1 : g_Xx1;
    __nv_bfloat16* d2 = ten ? g_Xa2 : g_Xx2;
    const int n0 = blockIdx.x * 32, c0 = blockIdx.y * 32;

    {
        int r = tid >> 3, n4 = (tid & 7) * 4;
        float4 v = *(const float4*)(src + ((size_t)b * CDIM + c0 + r) * NSP + n0 + n4);
        t[r][n4 + 0] = v.x; t[r][n4 + 1] = v.y;
        t[r][n4 + 2] = v.z; t[r][n4 + 3] = v.w;
    }
    __syncthreads();
    {
        int nr = tid >> 3, c4 = (tid & 7) * 4;
        u16 h[4], l[4];
        #pragma unroll
        for (int k = 0; k < 4; k++) bfsplit(t[c4 + k][nr], h[k], l[k]);
        uint2 hw, lw;
        hw.x = (u32)h[0] | ((u32)h[1] << 16); hw.y = (u32)h[2] | ((u32)h[3] << 16);
        lw.x = (u32)l[0] | ((u32)l[1] << 16); lw.y = (u32)l[2] | ((u32)l[3] << 16);
        size_t base = ((size_t)b * NSP + n0 + nr) * CDIM + c0 + c4;
        *(uint2*)&d1[base] = hw;
        *(uint2*)&d2[base] = lw;
    }
}

// ---------------------------------------------------------------------------
// Kernel C: proj via mma (3-pass split bf16 core).
// Q: single fp16 xLOG2E.  K: single fp16.  V: fp16 [c][n'] j-permuted.
// ---------------------------------------------------------------------------
#define PJ_X1 0
#define PJ_X2 33792
#define PJ_W  67584
#define PJ_ST 202752
#define PJ_B  220160
#define PJ_TOTAL 221184

__global__ __launch_bounds__(256, 1) void proj_mma(
    const float* __restrict__ bq, const float* __restrict__ bk,
    const float* __restrict__ bv)
{
    extern __shared__ __align__(16) char smem[];
    const u32 sb = smem_u32(smem);
    const int tid = threadIdx.x;
    const int lane = tid & 31, warp = tid >> 5;
    const int wr = warp >> 1, wc = warp & 1;
    const int gid = lane >> 2, tig = lane & 3;
    const int z = blockIdx.z, bb = blockIdx.y, n0 = blockIdx.x * 64;

    const __nv_bfloat16* xs1 = (z == 0) ? g_Xx1 : g_Xa1;
    const __nv_bfloat16* xs2 = (z == 0) ? g_Xx2 : g_Xa2;
    const __nv_bfloat16* w1 = g_W1[z];
    const __nv_bfloat16* w2 = g_W2[z];
    const float* bias = (z == 0) ? bq : (z == 1) ? bk : bv;

    float* bias_s = (float*)(smem + PJ_B);
    bias_s[tid] = bias[tid];

    #pragma unroll
    for (int it = 0; it < 8; it++) {
        int idx = it * 256 + tid;
        int j = idx >> 5, ch = idx & 31;
        size_t off = ((size_t)bb * NSP + n0 + j) * CDIM + ch * 8;
        CP16(sb + PJ_X1 + j * 528 + ch * 16, xs1 + off);
        CP16(sb + PJ_X2 + j * 528 + ch * 16, xs2 + off);
    }
    CPCOMMIT();

    auto issueW = [&](int oq) {
        u32 base = sb + PJ_W + (oq & 1) * 67584;
        #pragma unroll
        for (int it = 0; it < 8; it++) {
            int idx = it * 256 + tid;
            int o = idx >> 5, ch = idx & 31;
            size_t off = (size_t)(oq * 64 + o) * CDIM + ch * 8;
            CP16(base + o * 528 + ch * 16, w1 + off);
            CP16(base + 33792 + o * 528 + ch * 16, w2 + off);
        }
        CPCOMMIT();
    };
    issueW(0);

    const u32 aB1 = sb + PJ_X1 + (wr * 16 + (lane & 15)) * 528 + (lane >> 4) * 16;
    const u32 aB2 = sb + PJ_X2 + (wr * 16 + (lane & 15)) * 528 + (lane >> 4) * 16;
    const int bRow = wc * 32 + (lane & 7) + ((lane >> 4) << 3);
    const u32 bOffc = ((lane >> 3) & 1) * 16;

    for (int oq = 0; oq < 4; oq++) {
        CPWAIT(0);
        __syncthreads();
        if (oq < 3) issueW(oq + 1);

        u32 wbase = sb + PJ_W + (oq & 1) * 67584;
        u32 bB1 = wbase + bRow * 528 + bOffc;
        u32 bB2 = bB1 + 33792;

        float D[4][4];
        #pragma unroll
        for (int t = 0; t < 4; t++)
            #pragma unroll
            for (int e = 0; e < 4; e++) D[t][e] = 0.0f;

        #pragma unroll
        for (int kk = 0; kk < 16; kk++) {
            u32 a1[4], a2[4], bw1[8], bw2[8];
            ldsm4(a1, aB1 + kk * 32);
            ldsm4(a2, aB2 + kk * 32);
            ldsm4(bw1,     bB1 + kk * 32);
            ldsm4(bw1 + 4, bB1 + 16 * 528 + kk * 32);
            ldsm4(bw2,     bB2 + kk * 32);
            ldsm4(bw2 + 4, bB2 + 16 * 528 + kk * 32);
            #pragma unroll
            for (int t = 0; t < 4; t++) {
                mma_bf16(D[t], a1, bw1[2 * t], bw1[2 * t + 1]);
                mma_bf16(D[t], a1, bw2[2 * t], bw2[2 * t + 1]);
                mma_bf16(D[t], a2, bw1[2 * t], bw1[2 * t + 1]);
            }
        }

        if (z < 2) {
            __half* dst = (z == 0) ? g_Qh : g_Kh;
            const float sc = (z == 0) ? LOG2E : 1.0f;
            #pragma unroll
            for (int t = 0; t < 4; t++) {
                int o = oq * 64 + wc * 32 + t * 8 + 2 * tig;
                float b0 = bias_s[o], b1 = bias_s[o + 1];
                #pragma unroll
                for (int rh = 0; rh < 2; rh++) {
                    float f0 = (D[t][2 * rh + 0] + b0) * sc;
                    float f1 = (D[t][2 * rh + 1] + b1) * sc;
                    __half h0 = __float2half_rn(f0);
                    __half h1 = __float2half_rn(f1);
                    int n = n0 + wr * 16 + gid + rh * 8;
                    size_t idx = ((size_t)bb * NSP + n) * CDIM + o;
                    *(u32*)&dst[idx] =
                        (u32)__half_as_ushort(h0) | ((u32)__half_as_ushort(h1) << 16);
                }
            }
        } else {
            float* st = (float*)(smem + PJ_ST);
            #pragma unroll
            for (int t = 0; t < 4; t++) {
                int ol = wc * 32 + t * 8 + 2 * tig;
                float b0 = bias_s[oq * 64 + ol], b1 = bias_s[oq * 64 + ol + 1];
                #pragma unroll
                for (int rh = 0; rh < 2; rh++) {
                    int nl = wr * 16 + gid + rh * 8;
                    st[ol * 68 + nl]       = D[t][2 * rh + 0] + b0;
                    st[(ol + 1) * 68 + nl] = D[t][2 * rh + 1] + b1;
                }
            }
            __syncthreads();
            // fp16 store with j-perm within 8-groups: n' = (r&3)*2 + (r>>2)
            int ol = tid >> 2, nch = (tid & 3) * 16;
            u32 hv[8];
            #pragma unroll
            for (int m = 0; m < 8; m++) {
                int s = nch + 2 * m;
                int grp = s >> 3, r = s & 7;
                int o0 = (r >> 1);          // s even: orig col = r/2
                int o1 = (r >> 1) + 4;      // s odd slot: orig col = r/2 + 4
                float f0 = st[ol * 68 + grp * 8 + o0];
                float f1 = st[ol * 68 + grp * 8 + o1];
                __half h0 = __float2half_rn(f0);
                __half h1 = __float2half_rn(f1);
                hv[m] = (u32)__half_as_ushort(h0) | ((u32)__half_as_ushort(h1) << 16);
            }
            __half* dst = g_Vh + ((size_t)bb * CDIM + oq * 64 + ol) * NSP + n0 + nch;
            *(uint4*)&dst[0] = make_uint4(hv[0], hv[1], hv[2], hv[3]);
            *(uint4*)&dst[8] = make_uint4(hv[4], hv[5], hv[6], hv[7]);
        }
    }
}

// ---------------------------------------------------------------------------
// Kernel D: flash attention, 256 threads.
// S: warps (wr=warp>>1 i-slice16, wcs=warp&1 j-half), fp16 single-pass QK.
// PV: warps (wi=warp>>2 i-half32, wcq=warp&3 c-quarter64), tf32 P x fp16 V.
// ---------------------------------------------------------------------------
#define SQ   0
#define SK   33792
#define SVH  67584
#define SP   104448
#define SLR  121856
#define SM_TOTAL 122112
#define QK_STR 528
#define VH_STR 144
#define P_STR  272
#define OT_STR 258

__global__ __launch_bounds__(256, 1) void attn_kernel(
    const float* __restrict__ x, float* __restrict__ out)
{
    extern __shared__ __align__(16) char smem[];
    const u32 sb = smem_u32(smem);
    const int tid = threadIdx.x;
    const int lane = tid & 31;
    const int warp = tid >> 5;
    const int wr = warp >> 1, wcs = warp & 1;     // S roles
    const int wi = warp >> 2, wcq = warp & 3;     // PV roles
    const int gid = lane >> 2, tig = lane & 3;
    const int i0s = wr * 16, j0s = wcs * 32;
    const int i0p = wi * 32, c0q = wcq * 64;
    const int bb = blockIdx.y;
    const int n0 = blockIdx.x * BQ;

    float* lrow = (float*)(smem + SLR);
    if (tid < 64) lrow[tid] = 0.0f;

    const __half* qg  = g_Qh + ((size_t)bb * NSP + n0) * CDIM;
    const __half* khg = g_Kh + (size_t)bb * NSP * CDIM;
    const __half* vhg = g_Vh + (size_t)bb * CDIM * NSP;

    // ---- Q tile (fp16): 64 rows x 512B ----
    #pragma unroll
    for (int it = 0; it < 8; it++) {
        int idx = it * 256 + tid;
        int i = idx >> 5, ch = idx & 31;
        uint4 v = *(const uint4*)&qg[(size_t)i * CDIM + ch * 8];
        sts_v4(sb + SQ + i * QK_STR + ch * 16, v);
    }

    auto issueK = [&](int k0) {
        #pragma unroll
        for (int it = 0; it < 8; it++) {
            int idx = it * 256 + tid;
            int j = idx >> 5, ch = idx & 31;
            CP16(sb + SK + j * QK_STR + ch * 16, &khg[(size_t)(k0 + j) * CDIM + ch * 8]);
        }
        CPCOMMIT();
    };
    auto issueV = [&](int k0) {
        #pragma unroll
        for (int it = 0; it < 8; it++) {
            int idx = it * 256 + tid;
            int c = idx >> 3, ch = idx & 7;
            CP16(sb + SVH + c * VH_STR + ch * 16, &vhg[(size_t)c * NSP + k0 + ch * 8]);
        }
        CPCOMMIT();
    };

    issueK(0);
    issueV(0);

    const u32 aBase = sb + SQ + (i0s + (lane & 15)) * QK_STR + (lane >> 4) * 16;
    const int bRow = j0s + (lane & 7) + ((lane >> 4) << 3);
    const u32 bBase = sb + SK + bRow * QK_STR + ((lane >> 3) & 1) * 16;

    float O[2][8][4];
    #pragma unroll
    for (int it = 0; it < 2; it++)
        #pragma unroll
        for (int nt = 0; nt < 8; nt++)
            #pragma unroll
            for (int e = 0; e < 4; e++) O[it][nt][e] = 0.0f;
    float lsum0 = 0.0f, lsum1 = 0.0f;

    for (int kt = 0; kt < NK; kt++) {
        CPWAIT(1);                  // K(kt) ready
        __syncthreads();

        // ---- S = q * k : 16i x 32j per warp, fp16 single pass ----
        float S[4][4];
        #pragma unroll
        for (int t = 0; t < 4; t++)
            #pragma unroll
            for (int e = 0; e < 4; e++) S[t][e] = 0.0f;

        #pragma unroll
        for (int kk = 0; kk < 16; kk++) {
            u32 aq[4], bk[8];
            ldsm4(aq, aBase + kk * 32);
            ldsm4(bk,     bBase + kk * 32);
            ldsm4(bk + 4, bBase + 16 * QK_STR + kk * 32);
            #pragma unroll
            for (int t = 0; t < 4; t++)
                mma_f16(S[t], aq, bk[2 * t], bk[2 * t + 1]);
        }

        CPWAIT(0);                  // V(kt) ready; K fully read
        __syncthreads();
        issueK(((kt + 1) & (NK - 1)) * BK);

        // ---- P = exp2(S) (max-free), tf32 to smem (unpermuted) ----
        #pragma unroll
        for (int t = 0; t < 4; t++) {
            int jc = j0s + 8 * t + 2 * tig;
            float p0 = ex2f(S[t][0]), p1 = ex2f(S[t][1]);
            float p2 = ex2f(S[t][2]), p3 = ex2f(S[t][3]);
            lsum0 += p0 + p1;
            lsum1 += p2 + p3;
            sts_v2f(sb + SP + ((i0s + gid) * 68 + jc) * 4, tf32r(p0), tf32r(p1));
            sts_v2f(sb + SP + ((i0s + gid + 8) * 68 + jc) * 4, tf32r(p2), tf32r(p3));
        }
        BAR_GRP(1 + wi);            // warps 0-3 / 4-7 exchange P for their i-half

        // ---- O += P @ V^T : 32i x 64c per warp, tf32 x (fp16 V) ----
        const u32 pB = sb + SP + ((i0p + gid) * 68 + tig) * 4;
        const u32 vB = sb + SVH + (c0q + gid) * VH_STR + tig * 4;
        #pragma unroll
        for (int ks = 0; ks < 8; ks++) {
            u32 a[2][4];
            #pragma unroll
            for (int it = 0; it < 2; it++) {
                u32 pa = pB + it * 16 * P_STR + ks * 32;
                a[it][0] = lds_u32(pa);
                a[it][1] = lds_u32(pa + 8 * P_STR);
                a[it][2] = lds_u32(pa + 16);
                a[it][3] = lds_u32(pa + 8 * P_STR + 16);
            }
            #pragma unroll
            for (int nt = 0; nt < 8; nt++) {
                u32 vv = lds_u32(vB + nt * 8 * VH_STR + ks * 16);
                float2 bf = __half22float2(*(__half2*)&vv);
                u32 b0 = __float_as_uint(bf.x);
                u32 b1 = __float_as_uint(bf.y);
                mma_tf32(O[0][nt], a[0][0], a[0][1], a[0][2], a[0][3], b0, b1);
                mma_tf32(O[1][nt], a[1][0], a[1][1], a[1][2], a[1][3], b0, b1);
            }
        }
        __syncthreads();            // V (and P) fully read
        if (kt + 1 < NK) issueV((kt + 1) * BK);
    }

    CPWAIT(0);

    // ---- per-row l: quad reduce + atomic over 2 wcs warps ----
    lsum0 += __shfl_xor_sync(0xffffffffu, lsum0, 1);
    lsum0 += __shfl_xor_sync(0xffffffffu, lsum0, 2);
    lsum1 += __shfl_xor_sync(0xffffffffu, lsum1, 1);
    lsum1 += __shfl_xor_sync(0xffffffffu, lsum1, 2);
    if (tig == 0) {
        atomicAdd(&lrow[i0s + gid], lsum0);
        atomicAdd(&lrow[i0s + gid + 8], lsum1);
    }
    __syncthreads();

    // ---- transpose O through smem (reuse SQ/SK region) ----
    #pragma unroll
    for (int it = 0; it < 2; it++)
        #pragma unroll
        for (int nt = 0; nt < 8; nt++) {
            int i = i0p + it * 16 + gid;
            int c = c0q + nt * 8 + 2 * tig;
            sts_v2f(sb + (i * OT_STR + c) * 4, O[it][nt][0], O[it][nt][1]);
            sts_v2f(sb + ((i + 8) * OT_STR + c) * 4, O[it][nt][2], O[it][nt][3]);
        }
    __syncthreads();

    // ---- out = O/l + x, coalesced ----
    const float* xb = x + (size_t)bb * CDIM * NSP;
    float* ob = out + (size_t)bb * CDIM * NSP;
    const int i = tid & 63;
    const int cg = tid >> 6;
    const float invl = 1.0f / lrow[i];
    #pragma unroll 4
    for (int cc = 0; cc < 64; cc++) {
        int c = cc * 4 + cg;
        float ov = lds_f32(sb + (i * OT_STR + c) * 4);
        size_t g = (size_t)c * NSP + n0 + i;
        ob[g] = ov * invl + xb[g];
    }
}

// ---------------------------------------------------------------------------
extern "C" void kernel_launch(void* const* d_in, const int* in_sizes, int n_in,
                              void* d_out, int out_size)
{
    const float* x    = (const float*)d_in[0];
    const float* attr = (const float*)d_in[1];
    const float* Wq   = (const float*)d_in[2];
    const float* bq   = (const float*)d_in[3];
    const float* Wk   = (const float*)d_in[4];
    const float* bk   = (const float*)d_in[5];
    const float* Wv   = (const float*)d_in[6];
    const float* bv   = (const float*)d_in[7];
    float* out = (float*)d_out;

    cudaFuncSetAttribute(proj_mma,
                         cudaFuncAttributeMaxDynamicSharedMemorySize, PJ_TOTAL);
    cudaFuncSetAttribute(attn_kernel,
                         cudaFuncAttributeMaxDynamicSharedMemorySize, SM_TOTAL);

    split_w<<<768, 256>>>(Wq, Wk, Wv);
    split_x<<<dim3(NSP / 32, CDIM / 32, NB * 2), 256>>>(x, attr);
    proj_mma<<<dim3(NSP / 64, NB, 3), 256, PJ_TOTAL>>>(bq, bk, bv);
    attn_kernel<<<dim3(NSP / BQ, NB), 256, SM_TOTAL>>>(x, out);
}

// round 11
// speedup vs baseline: 1.4129x; 1.0068x over previous
#include <cuda_runtime.h>
#include <cuda_bf16.h>
#include <cuda_fp16.h>

#define NSP 4096
#define CDIM 256
#define NB 8
#define BQ 64
#define BK 32
#define NK (NSP / BK)
#define LOG2E 1.4426950408889634f

// ---- scratch ----
__device__ __align__(256) __half g_Qh[(size_t)NB * NSP * CDIM];   // [b][n][c] fp16 (xLOG2E)
__device__ __align__(256) __half g_Kh[(size_t)NB * NSP * CDIM];   // [b][n][c] fp16
__device__ __align__(256) __half g_Vh[(size_t)NB * CDIM * NSP];   // [b][c][n'] fp16, j-perm
__device__ __align__(256) __nv_bfloat16 g_Xx1[(size_t)NB * NSP * CDIM];
__device__ __align__(256) __nv_bfloat16 g_Xx2[(size_t)NB * NSP * CDIM];
__device__ __align__(256) __nv_bfloat16 g_Xa1[(size_t)NB * NSP * CDIM];
__device__ __align__(256) __nv_bfloat16 g_Xa2[(size_t)NB * NSP * CDIM];
__device__ __align__(256) __nv_bfloat16 g_W1[3][65536];
__device__ __align__(256) __nv_bfloat16 g_W2[3][65536];

typedef unsigned long long u64;
typedef unsigned int u32;
typedef unsigned short u16;

// ================= helpers =================
__device__ __forceinline__ u32 smem_u32(const void* p) {
    u32 a;
    asm("{ .reg .u64 t; cvta.to.shared.u64 t, %1; cvt.u32.u64 %0, t; }" : "=r"(a) : "l"(p));
    return a;
}
__device__ __forceinline__ float tf32r(float f) {
    float o; asm("cvt.rna.tf32.f32 %0, %1;" : "=f"(o) : "f"(f)); return o;
}
__device__ __forceinline__ float ex2f(float x) {
    float y; asm("ex2.approx.f32 %0, %1;" : "=f"(y) : "f"(x)); return y;
}
__device__ __forceinline__ void ldsm4(u32* r, u32 addr) {
    asm volatile("ldmatrix.sync.aligned.m8n8.x4.shared.b16 {%0,%1,%2,%3}, [%4];"
                 : "=r"(r[0]), "=r"(r[1]), "=r"(r[2]), "=r"(r[3]) : "r"(addr));
}
__device__ __forceinline__ void mma_bf16(float* d, const u32* a, u32 b0, u32 b1) {
    asm volatile(
        "mma.sync.aligned.m16n8k16.row.col.f32.bf16.bf16.f32 "
        "{%0,%1,%2,%3}, {%4,%5,%6,%7}, {%8,%9}, {%0,%1,%2,%3};"
        : "+f"(d[0]), "+f"(d[1]), "+f"(d[2]), "+f"(d[3])
        : "r"(a[0]), "r"(a[1]), "r"(a[2]), "r"(a[3]), "r"(b0), "r"(b1));
}
__device__ __forceinline__ void mma_f16(float* d, const u32* a, u32 b0, u32 b1) {
    asm volatile(
        "mma.sync.aligned.m16n8k16.row.col.f32.f16.f16.f32 "
        "{%0,%1,%2,%3}, {%4,%5,%6,%7}, {%8,%9}, {%0,%1,%2,%3};"
        : "+f"(d[0]), "+f"(d[1]), "+f"(d[2]), "+f"(d[3])
        : "r"(a[0]), "r"(a[1]), "r"(a[2]), "r"(a[3]), "r"(b0), "r"(b1));
}
__device__ __forceinline__ void mma_tf32(float* d, u32 a0, u32 a1, u32 a2, u32 a3,
                                         u32 b0, u32 b1) {
    asm volatile(
        "mma.sync.aligned.m16n8k8.row.col.f32.tf32.tf32.f32 "
        "{%0,%1,%2,%3}, {%4,%5,%6,%7}, {%8,%9}, {%0,%1,%2,%3};"
        : "+f"(d[0]), "+f"(d[1]), "+f"(d[2]), "+f"(d[3])
        : "r"(a0), "r"(a1), "r"(a2), "r"(a3), "r"(b0), "r"(b1));
}
__device__ __forceinline__ u32 lds_u32(u32 a) {
    u32 v; asm volatile("ld.shared.b32 %0, [%1];" : "=r"(v) : "r"(a)); return v;
}
__device__ __forceinline__ float lds_f32(u32 a) {
    float v; asm volatile("ld.shared.f32 %0, [%1];" : "=f"(v) : "r"(a)); return v;
}
__device__ __forceinline__ void sts_v2f(u32 a, float x, float y) {
    asm volatile("st.shared.v2.f32 [%0], {%1,%2};" :: "r"(a), "f"(x), "f"(y) : "memory");
}
__device__ __forceinline__ void sts_v4(u32 a, uint4 v) {
    asm volatile("st.shared.v4.b32 [%0], {%1,%2,%3,%4};"
                 :: "r"(a), "r"(v.x), "r"(v.y), "r"(v.z), "r"(v.w) : "memory");
}
#define CP16(dst, src) asm volatile("cp.async.cg.shared.global [%0], [%1], 16;" \
    :: "r"(dst), "l"(src) : "memory")
#define CPCOMMIT() asm volatile("cp.async.commit_group;" ::: "memory")
#define CPWAIT(n)  asm volatile("cp.async.wait_group %0;" :: "n"(n) : "memory")
#define BAR_GRP(id) asm volatile("bar.sync %0, %1;" :: "r"(id), "r"(128) : "memory")

__device__ __forceinline__ void bfsplit(float f, u16& hi, u16& lo) {
    __nv_bfloat16 h = __float2bfloat16_rn(f);
    __nv_bfloat16 l = __float2bfloat16_rn(f - __bfloat162float(h));
    hi = __bfloat16_as_ushort(h);
    lo = __bfloat16_as_ushort(l);
}

// ---------------------------------------------------------------------------
// Kernel A: split weights into bf16 hi/lo pairs.
// ---------------------------------------------------------------------------
__global__ __launch_bounds__(256) void split_w(
    const float* __restrict__ Wq, const float* __restrict__ Wk,
    const float* __restrict__ Wv)
{
    int idx = blockIdx.x * 256 + threadIdx.x;
    int which = idx >> 16;
    int i = idx & 65535;
    const float* W = (which == 0) ? Wq : (which == 1) ? Wk : Wv;
    u16 h, l;
    bfsplit(W[i], h, l);
    g_W1[which][i] = __ushort_as_bfloat16(h);
    g_W2[which][i] = __ushort_as_bfloat16(l);
}

// ---------------------------------------------------------------------------
// Kernel B: split + transpose x/attr -> [b][n][c] bf16 hi/lo.
// ---------------------------------------------------------------------------
__global__ __launch_bounds__(256) void split_x(
    const float* __restrict__ x, const float* __restrict__ attr)
{
    __shared__ float t[32][33];
    const int tid = threadIdx.x;
    const int b = blockIdx.z >> 1, ten = blockIdx.z & 1;
    const float* src = ten ? attr : x;
    __nv_bfloat16* d1 = ten ? g_Xa1 : g_Xx1;
    __nv_bfloat16* d2 = ten ? g_Xa2 : g_Xx2;
    const int n0 = blockIdx.x * 32, c0 = blockIdx.y * 32;

    {
        int r = tid >> 3, n4 = (tid & 7) * 4;
        float4 v = *(const float4*)(src + ((size_t)b * CDIM + c0 + r) * NSP + n0 + n4);
        t[r][n4 + 0] = v.x; t[r][n4 + 1] = v.y;
        t[r][n4 + 2] = v.z; t[r][n4 + 3] = v.w;
    }
    __syncthreads();
    {
        int nr = tid >> 3, c4 = (tid & 7) * 4;
        u16 h[4], l[4];
        #pragma unroll
        for (int k = 0; k < 4; k++) bfsplit(t[c4 + k][nr], h[k], l[k]);
        uint2 hw, lw;
        hw.x = (u32)h[0] | ((u32)h[1] << 16); hw.y = (u32)h[2] | ((u32)h[3] << 16);
        lw.x = (u32)l[0] | ((u32)l[1] << 16); lw.y = (u32)l[2] | ((u32)l[3] << 16);
        size_t base = ((size_t)b * NSP + n0 + nr) * CDIM + c0 + c4;
        *(uint2*)&d1[base] = hw;
        *(uint2*)&d2[base] = lw;
    }
}

// ---------------------------------------------------------------------------
// Kernel C: proj via mma (3-pass split bf16 core).
// Q: single fp16 xLOG2E.  K: single fp16.  V: fp16 [c][n'] j-permuted.
// ---------------------------------------------------------------------------
#define PJ_X1 0
#define PJ_X2 33792
#define PJ_W  67584
#define PJ_ST 202752
#define PJ_B  220160
#define PJ_TOTAL 221184

__global__ __launch_bounds__(256, 1) void proj_mma(
    const float* __restrict__ bq, const float* __restrict__ bk,
    const float* __restrict__ bv)
{
    extern __shared__ __align__(16) char smem[];
    const u32 sb = smem_u32(smem);
    const int tid = threadIdx.x;
    const int lane = tid & 31, warp = tid >> 5;
    const int wr = warp >> 1, wc = warp & 1;
    const int gid = lane >> 2, tig = lane & 3;
    const int z = blockIdx.z, bb = blockIdx.y, n0 = blockIdx.x * 64;

    const __nv_bfloat16* xs1 = (z == 0) ? g_Xx1 : g_Xa1;
    const __nv_bfloat16* xs2 = (z == 0) ? g_Xx2 : g_Xa2;
    const __nv_bfloat16* w1 = g_W1[z];
    const __nv_bfloat16* w2 = g_W2[z];
    const float* bias = (z == 0) ? bq : (z == 1) ? bk : bv;

    float* bias_s = (float*)(smem + PJ_B);
    bias_s[tid] = bias[tid];

    #pragma unroll
    for (int it = 0; it < 8; it++) {
        int idx = it * 256 + tid;
        int j = idx >> 5, ch = idx & 31;
        size_t off = ((size_t)bb * NSP + n0 + j) * CDIM + ch * 8;
        CP16(sb + PJ_X1 + j * 528 + ch * 16, xs1 + off);
        CP16(sb + PJ_X2 + j * 528 + ch * 16, xs2 + off);
    }
    CPCOMMIT();

    auto issueW = [&](int oq) {
        u32 base = sb + PJ_W + (oq & 1) * 67584;
        #pragma unroll
        for (int it = 0; it < 8; it++) {
            int idx = it * 256 + tid;
            int o = idx >> 5, ch = idx & 31;
            size_t off = (size_t)(oq * 64 + o) * CDIM + ch * 8;
            CP16(base + o * 528 + ch * 16, w1 + off);
            CP16(base + 33792 + o * 528 + ch * 16, w2 + off);
        }
        CPCOMMIT();
    };
    issueW(0);

    const u32 aB1 = sb + PJ_X1 + (wr * 16 + (lane & 15)) * 528 + (lane >> 4) * 16;
    const u32 aB2 = sb + PJ_X2 + (wr * 16 + (lane & 15)) * 528 + (lane >> 4) * 16;
    const int bRow = wc * 32 + (lane & 7) + ((lane >> 4) << 3);
    const u32 bOffc = ((lane >> 3) & 1) * 16;

    for (int oq = 0; oq < 4; oq++) {
        CPWAIT(0);
        __syncthreads();
        if (oq < 3) issueW(oq + 1);

        u32 wbase = sb + PJ_W + (oq & 1) * 67584;
        u32 bB1 = wbase + bRow * 528 + bOffc;
        u32 bB2 = bB1 + 33792;

        float D[4][4];
        #pragma unroll
        for (int t = 0; t < 4; t++)
            #pragma unroll
            for (int e = 0; e < 4; e++) D[t][e] = 0.0f;

        #pragma unroll
        for (int kk = 0; kk < 16; kk++) {
            u32 a1[4], a2[4], bw1[8], bw2[8];
            ldsm4(a1, aB1 + kk * 32);
            ldsm4(a2, aB2 + kk * 32);
            ldsm4(bw1,     bB1 + kk * 32);
            ldsm4(bw1 + 4, bB1 + 16 * 528 + kk * 32);
            ldsm4(bw2,     bB2 + kk * 32);
            ldsm4(bw2 + 4, bB2 + 16 * 528 + kk * 32);
            #pragma unroll
            for (int t = 0; t < 4; t++) {
                mma_bf16(D[t], a1, bw1[2 * t], bw1[2 * t + 1]);
                mma_bf16(D[t], a1, bw2[2 * t], bw2[2 * t + 1]);
                mma_bf16(D[t], a2, bw1[2 * t], bw1[2 * t + 1]);
            }
        }

        if (z < 2) {
            __half* dst = (z == 0) ? g_Qh : g_Kh;
            const float sc = (z == 0) ? LOG2E : 1.0f;
            #pragma unroll
            for (int t = 0; t < 4; t++) {
                int o = oq * 64 + wc * 32 + t * 8 + 2 * tig;
                float b0 = bias_s[o], b1 = bias_s[o + 1];
                #pragma unroll
                for (int rh = 0; rh < 2; rh++) {
                    float f0 = (D[t][2 * rh + 0] + b0) * sc;
                    float f1 = (D[t][2 * rh + 1] + b1) * sc;
                    __half h0 = __float2half_rn(f0);
                    __half h1 = __float2half_rn(f1);
                    int n = n0 + wr * 16 + gid + rh * 8;
                    size_t idx = ((size_t)bb * NSP + n) * CDIM + o;
                    *(u32*)&dst[idx] =
                        (u32)__half_as_ushort(h0) | ((u32)__half_as_ushort(h1) << 16);
                }
            }
        } else {
            float* st = (float*)(smem + PJ_ST);
            #pragma unroll
            for (int t = 0; t < 4; t++) {
                int ol = wc * 32 + t * 8 + 2 * tig;
                float b0 = bias_s[oq * 64 + ol], b1 = bias_s[oq * 64 + ol + 1];
                #pragma unroll
                for (int rh = 0; rh < 2; rh++) {
                    int nl = wr * 16 + gid + rh * 8;
                    st[ol * 68 + nl]       = D[t][2 * rh + 0] + b0;
                    st[(ol + 1) * 68 + nl] = D[t][2 * rh + 1] + b1;
                }
            }
            __syncthreads();
            // fp16 store with j-perm within 8-groups
            int ol = tid >> 2, nch = (tid & 3) * 16;
            u32 hv[8];
            #pragma unroll
            for (int m = 0; m < 8; m++) {
                int s = nch + 2 * m;
                int grp = s >> 3, r = s & 7;
                int o0 = (r >> 1);
                int o1 = (r >> 1) + 4;
                float f0 = st[ol * 68 + grp * 8 + o0];
                float f1 = st[ol * 68 + grp * 8 + o1];
                __half h0 = __float2half_rn(f0);
                __half h1 = __float2half_rn(f1);
                hv[m] = (u32)__half_as_ushort(h0) | ((u32)__half_as_ushort(h1) << 16);
            }
            __half* dst = g_Vh + ((size_t)bb * CDIM + oq * 64 + ol) * NSP + n0 + nch;
            *(uint4*)&dst[0] = make_uint4(hv[0], hv[1], hv[2], hv[3]);
            *(uint4*)&dst[8] = make_uint4(hv[4], hv[5], hv[6], hv[7]);
        }
    }
}

// ---------------------------------------------------------------------------
// Kernel D: flash attention, 256 threads, BK=32, 2 CTAs/SM.
// S: wr=warp>>1 (i-slice16), wcs=warp&1 (j-half16).  fp16 QK.
// PV: wi=warp>>2 (i-half32), wcq=warp&3 (c-quarter64).  tf32 P x fp16 V.
// ---------------------------------------------------------------------------
#define SQ   0
#define SK   33792
#define SVH  50688
#define SP   71168
#define SLR  80384
#define SM_TOTAL 80640
#define QK_STR 528
#define VH_STR 80
#define P_STR  144
#define OT_STR 258

__global__ __launch_bounds__(256, 2) void attn_kernel(
    const float* __restrict__ x, float* __restrict__ out)
{
    extern __shared__ __align__(16) char smem[];
    const u32 sb = smem_u32(smem);
    const int tid = threadIdx.x;
    const int lane = tid & 31;
    const int warp = tid >> 5;
    const int wr = warp >> 1, wcs = warp & 1;     // S roles
    const int wi = warp >> 2, wcq = warp & 3;     // PV roles
    const int gid = lane >> 2, tig = lane & 3;
    const int i0s = wr * 16, j0s = wcs * 16;
    const int i0p = wi * 32, c0q = wcq * 64;
    const int bb = blockIdx.y;
    const int n0 = blockIdx.x * BQ;

    float* lrow = (float*)(smem + SLR);
    if (tid < 64) lrow[tid] = 0.0f;

    const __half* qg  = g_Qh + ((size_t)bb * NSP + n0) * CDIM;
    const __half* khg = g_Kh + (size_t)bb * NSP * CDIM;
    const __half* vhg = g_Vh + (size_t)bb * CDIM * NSP;

    // ---- Q tile (fp16): 64 rows x 512B ----
    #pragma unroll
    for (int it = 0; it < 8; it++) {
        int idx = it * 256 + tid;
        int i = idx >> 5, ch = idx & 31;
        uint4 v = *(const uint4*)&qg[(size_t)i * CDIM + ch * 8];
        sts_v4(sb + SQ + i * QK_STR + ch * 16, v);
    }

    auto issueK = [&](int k0) {
        #pragma unroll
        for (int it = 0; it < 4; it++) {
            int idx = it * 256 + tid;
            int j = idx >> 5, ch = idx & 31;
            CP16(sb + SK + j * QK_STR + ch * 16, &khg[(size_t)(k0 + j) * CDIM + ch * 8]);
        }
        CPCOMMIT();
    };
    auto issueV = [&](int k0) {
        #pragma unroll
        for (int it = 0; it < 4; it++) {
            int idx = it * 256 + tid;
            int c = idx >> 2, ch = idx & 3;
            CP16(sb + SVH + c * VH_STR + ch * 16, &vhg[(size_t)c * NSP + k0 + ch * 8]);
        }
        CPCOMMIT();
    };

    issueK(0);
    issueV(0);

    const u32 aBase = sb + SQ + (i0s + (lane & 15)) * QK_STR + (lane >> 4) * 16;
    const int bRow = j0s + (lane & 7) + ((lane >> 4) << 3);
    const u32 bBase = sb + SK + bRow * QK_STR + ((lane >> 3) & 1) * 16;

    float O[2][8][4];
    #pragma unroll
    for (int it = 0; it < 2; it++)
        #pragma unroll
        for (int nt = 0; nt < 8; nt++)
            #pragma unroll
            for (int e = 0; e < 4; e++) O[it][nt][e] = 0.0f;
    float lsum0 = 0.0f, lsum1 = 0.0f;

    for (int kt = 0; kt < NK; kt++) {
        CPWAIT(1);                  // K(kt) ready
        __syncthreads();

        // ---- S = q * k : 16i x 16j per warp, fp16 ----
        float S[2][4];
        #pragma unroll
        for (int t = 0; t < 2; t++)
            #pragma unroll
            for (int e = 0; e < 4; e++) S[t][e] = 0.0f;

        #pragma unroll
        for (int kk = 0; kk < 16; kk++) {
            u32 aq[4], bk[4];
            ldsm4(aq, aBase + kk * 32);
            ldsm4(bk, bBase + kk * 32);
            mma_f16(S[0], aq, bk[0], bk[1]);
            mma_f16(S[1], aq, bk[2], bk[3]);
        }

        CPWAIT(0);                  // V(kt) ready; K fully read
        __syncthreads();
        issueK(((kt + 1) & (NK - 1)) * BK);

        // ---- P = exp2(S) (max-free), tf32 to smem ----
        #pragma unroll
        for (int t = 0; t < 2; t++) {
            int jc = j0s + 8 * t + 2 * tig;
            float p0 = ex2f(S[t][0]), p1 = ex2f(S[t][1]);
            float p2 = ex2f(S[t][2]), p3 = ex2f(S[t][3]);
            lsum0 += p0 + p1;
            lsum1 += p2 + p3;
            sts_v2f(sb + SP + ((i0s + gid) * 36 + jc) * 4, tf32r(p0), tf32r(p1));
            sts_v2f(sb + SP + ((i0s + gid + 8) * 36 + jc) * 4, tf32r(p2), tf32r(p3));
        }
        BAR_GRP(1 + wi);            // warps 0-3 / 4-7 exchange P for their i-half

        // ---- O += P @ V^T : 32i x 64c per warp, tf32 x (fp16 V), k=32 ----
        const u32 pB = sb + SP + ((i0p + gid) * 36 + tig) * 4;
        const u32 vB = sb + SVH + (c0q + gid) * VH_STR + tig * 4;
        #pragma unroll
        for (int ks = 0; ks < 4; ks++) {
            u32 a[2][4];
            #pragma unroll
            for (int it = 0; it < 2; it++) {
                u32 pa = pB + it * 16 * P_STR + ks * 32;
                a[it][0] = lds_u32(pa);
                a[it][1] = lds_u32(pa + 8 * P_STR);
                a[it][2] = lds_u32(pa + 16);
                a[it][3] = lds_u32(pa + 8 * P_STR + 16);
            }
            #pragma unroll
            for (int nt = 0; nt < 8; nt++) {
                u32 vv = lds_u32(vB + nt * 8 * VH_STR + ks * 16);
                float2 bf = __half22float2(*(__half2*)&vv);
                u32 b0 = __float_as_uint(bf.x);
                u32 b1 = __float_as_uint(bf.y);
                mma_tf32(O[0][nt], a[0][0], a[0][1], a[0][2], a[0][3], b0, b1);
                mma_tf32(O[1][nt], a[1][0], a[1][1], a[1][2], a[1][3], b0, b1);
            }
        }
        __syncthreads();            // V (and P) fully read
        if (kt + 1 < NK) issueV((kt + 1) * BK);
    }

    CPWAIT(0);

    // ---- per-row l: quad reduce + atomic over 2 wcs warps ----
    lsum0 += __shfl_xor_sync(0xffffffffu, lsum0, 1);
    lsum0 += __shfl_xor_sync(0xffffffffu, lsum0, 2);
    lsum1 += __shfl_xor_sync(0xffffffffu, lsum1, 1);
    lsum1 += __shfl_xor_sync(0xffffffffu, lsum1, 2);
    if (tig == 0) {
        atomicAdd(&lrow[i0s + gid], lsum0);
        atomicAdd(&lrow[i0s + gid + 8], lsum1);
    }
    __syncthreads();

    // ---- transpose O through smem (reuse SQ/SK region) ----
    #pragma unroll
    for (int it = 0; it < 2; it++)
        #pragma unroll
        for (int nt = 0; nt < 8; nt++) {
            int i = i0p + it * 16 + gid;
            int c = c0q + nt * 8 + 2 * tig;
            sts_v2f(sb + (i * OT_STR + c) * 4, O[it][nt][0], O[it][nt][1]);
            sts_v2f(sb + ((i + 8) * OT_STR + c) * 4, O[it][nt][2], O[it][nt][3]);
        }
    __syncthreads();

    // ---- out = O/l + x, coalesced ----
    const float* xb = x + (size_t)bb * CDIM * NSP;
    float* ob = out + (size_t)bb * CDIM * NSP;
    const int i = tid & 63;
    const int cg = tid >> 6;
    const float invl = 1.0f / lrow[i];
    #pragma unroll 4
    for (int cc = 0; cc < 64; cc++) {
        int c = cc * 4 + cg;
        float ov = lds_f32(sb + (i * OT_STR + c) * 4);
        size_t g = (size_t)c * NSP + n0 + i;
        ob[g] = ov * invl + xb[g];
    }
}

// ---------------------------------------------------------------------------
extern "C" void kernel_launch(void* const* d_in, const int* in_sizes, int n_in,
                              void* d_out, int out_size)
{
    const float* x    = (const float*)d_in[0];
    const float* attr = (const float*)d_in[1];
    const float* Wq   = (const float*)d_in[2];
    const float* bq   = (const float*)d_in[3];
    const float* Wk   = (const float*)d_in[4];
    const float* bk   = (const float*)d_in[5];
    const float* Wv   = (const float*)d_in[6];
    const float* bv   = (const float*)d_in[7];
    float* out = (float*)d_out;

    cudaFuncSetAttribute(proj_mma,
                         cudaFuncAttributeMaxDynamicSharedMemorySize, PJ_TOTAL);
    cudaFuncSetAttribute(attn_kernel,
                         cudaFuncAttributeMaxDynamicSharedMemorySize, SM_TOTAL);

    split_w<<<768, 256>>>(Wq, Wk, Wv);
    split_x<<<dim3(NSP / 32, CDIM / 32, NB * 2), 256>>>(x, attr);
    proj_mma<<<dim3(NSP / 64, NB, 3), 256, PJ_TOTAL>>>(bq, bk, bv);
    attn_kernel<<<dim3(NSP / BQ, NB), 256, SM_TOTAL>>>(x, out);
}

// round 12
// speedup vs baseline: 1.4346x; 1.0154x over previous
#include <cuda_runtime.h>
#include <cuda_bf16.h>
#include <cuda_fp16.h>

#define NSP 4096
#define CDIM 256
#define NB 8
#define BQ 64
#define BK 32
#define NK (NSP / BK)
#define LOG2E 1.4426950408889634f

// ---- scratch ----
__device__ __align__(256) __half g_Qh[(size_t)NB * NSP * CDIM];   // [b][n][c] fp16 (xLOG2E)
__device__ __align__(256) __half g_Kh[(size_t)NB * NSP * CDIM];   // [b][n][c] fp16
__device__ __align__(256) __half g_Vh[(size_t)NB * CDIM * NSP];   // [b][c][n] fp16 natural
__device__ __align__(256) __nv_bfloat16 g_Xx1[(size_t)NB * NSP * CDIM];
__device__ __align__(256) __nv_bfloat16 g_Xx2[(size_t)NB * NSP * CDIM];
__device__ __align__(256) __nv_bfloat16 g_Xa1[(size_t)NB * NSP * CDIM];
__device__ __align__(256) __nv_bfloat16 g_Xa2[(size_t)NB * NSP * CDIM];
__device__ __align__(256) __nv_bfloat16 g_W1[3][65536];
__device__ __align__(256) __nv_bfloat16 g_W2[3][65536];

typedef unsigned long long u64;
typedef unsigned int u32;
typedef unsigned short u16;

// ================= helpers =================
__device__ __forceinline__ u32 smem_u32(const void* p) {
    u32 a;
    asm("{ .reg .u64 t; cvta.to.shared.u64 t, %1; cvt.u32.u64 %0, t; }" : "=r"(a) : "l"(p));
    return a;
}
__device__ __forceinline__ float ex2f(float x) {
    float y; asm("ex2.approx.f32 %0, %1;" : "=f"(y) : "f"(x)); return y;
}
__device__ __forceinline__ void ldsm4(u32* r, u32 addr) {
    asm volatile("ldmatrix.sync.aligned.m8n8.x4.shared.b16 {%0,%1,%2,%3}, [%4];"
                 : "=r"(r[0]), "=r"(r[1]), "=r"(r[2]), "=r"(r[3]) : "r"(addr));
}
__device__ __forceinline__ void mma_bf16(float* d, const u32* a, u32 b0, u32 b1) {
    asm volatile(
        "mma.sync.aligned.m16n8k16.row.col.f32.bf16.bf16.f32 "
        "{%0,%1,%2,%3}, {%4,%5,%6,%7}, {%8,%9}, {%0,%1,%2,%3};"
        : "+f"(d[0]), "+f"(d[1]), "+f"(d[2]), "+f"(d[3])
        : "r"(a[0]), "r"(a[1]), "r"(a[2]), "r"(a[3]), "r"(b0), "r"(b1));
}
__device__ __forceinline__ void mma_f16(float* d, const u32* a, u32 b0, u32 b1) {
    asm volatile(
        "mma.sync.aligned.m16n8k16.row.col.f32.f16.f16.f32 "
        "{%0,%1,%2,%3}, {%4,%5,%6,%7}, {%8,%9}, {%0,%1,%2,%3};"
        : "+f"(d[0]), "+f"(d[1]), "+f"(d[2]), "+f"(d[3])
        : "r"(a[0]), "r"(a[1]), "r"(a[2]), "r"(a[3]), "r"(b0), "r"(b1));
}
__device__ __forceinline__ u32 lds_u32(u32 a) {
    u32 v; asm volatile("ld.shared.b32 %0, [%1];" : "=r"(v) : "r"(a)); return v;
}
__device__ __forceinline__ float lds_f32(u32 a) {
    float v; asm volatile("ld.shared.f32 %0, [%1];" : "=f"(v) : "r"(a)); return v;
}
__device__ __forceinline__ void sts_u32(u32 a, u32 v) {
    asm volatile("st.shared.b32 [%0], %1;" :: "r"(a), "r"(v) : "memory");
}
__device__ __forceinline__ void sts_f32(u32 a, float v) {
    asm volatile("st.shared.f32 [%0], %1;" :: "r"(a), "f"(v) : "memory");
}
__device__ __forceinline__ void sts_v2f(u32 a, float x, float y) {
    asm volatile("st.shared.v2.f32 [%0], {%1,%2};" :: "r"(a), "f"(x), "f"(y) : "memory");
}
__device__ __forceinline__ void sts_v4(u32 a, uint4 v) {
    asm volatile("st.shared.v4.b32 [%0], {%1,%2,%3,%4};"
                 :: "r"(a), "r"(v.x), "r"(v.y), "r"(v.z), "r"(v.w) : "memory");
}
#define CP16(dst, src) asm volatile("cp.async.cg.shared.global [%0], [%1], 16;" \
    :: "r"(dst), "l"(src) : "memory")
#define CPCOMMIT() asm volatile("cp.async.commit_group;" ::: "memory")
#define CPWAIT(n)  asm volatile("cp.async.wait_group %0;" :: "n"(n) : "memory")
#define BAR_GRP(id) asm volatile("bar.sync %0, %1;" :: "r"(id), "r"(128) : "memory")

__device__ __forceinline__ void bfsplit(float f, u16& hi, u16& lo) {
    __nv_bfloat16 h = __float2bfloat16_rn(f);
    __nv_bfloat16 l = __float2bfloat16_rn(f - __bfloat162float(h));
    hi = __bfloat16_as_ushort(h);
    lo = __bfloat16_as_ushort(l);
}
__device__ __forceinline__ u32 packh2(float a, float b) {
    __half h0 = __float2half_rn(a);
    __half h1 = __float2half_rn(b);
    return (u32)__half_as_ushort(h0) | ((u32)__half_as_ushort(h1) << 16);
}

// ---------------------------------------------------------------------------
// Kernel A: split weights into bf16 hi/lo pairs.
// ---------------------------------------------------------------------------
__global__ __launch_bounds__(256) void split_w(
    const float* __restrict__ Wq, const float* __restrict__ Wk,
    const float* __restrict__ Wv)
{
    int idx = blockIdx.x * 256 + threadIdx.x;
    int which = idx >> 16;
    int i = idx & 65535;
    const float* W = (which == 0) ? Wq : (which == 1) ? Wk : Wv;
    u16 h, l;
    bfsplit(W[i], h, l);
    g_W1[which][i] = __ushort_as_bfloat16(h);
    g_W2[which][i] = __ushort_as_bfloat16(l);
}

// ---------------------------------------------------------------------------
// Kernel B: split + transpose x/attr -> [b][n][c] bf16 hi/lo.
// ---------------------------------------------------------------------------
__global__ __launch_bounds__(256) void split_x(
    const float* __restrict__ x, const float* __restrict__ attr)
{
    __shared__ float t[32][33];
    const int tid = threadIdx.x;
    const int b = blockIdx.z >> 1, ten = blockIdx.z & 1;
    const float* src = ten ? attr : x;
    __nv_bfloat16* d1 = ten ? g_Xa1 : g_Xx1;
    __nv_bfloat16* d2 = ten ? g_Xa2 : g_Xx2;
    const int n0 = blockIdx.x * 32, c0 = blockIdx.y * 32;

    {
        int r = tid >> 3, n4 = (tid & 7) * 4;
        float4 v = *(const float4*)(src + ((size_t)b * CDIM + c0 + r) * NSP + n0 + n4);
        t[r][n4 + 0] = v.x; t[r][n4 + 1] = v.y;
        t[r][n4 + 2] = v.z; t[r][n4 + 3] = v.w;
    }
    __syncthreads();
    {
        int nr = tid >> 3, c4 = (tid & 7) * 4;
        u16 h[4], l[4];
        #pragma unroll
        for (int k = 0; k < 4; k++) bfsplit(t[c4 + k][nr], h[k], l[k]);
        uint2 hw, lw;
        hw.x = (u32)h[0] | ((u32)h[1] << 16); hw.y = (u32)h[2] | ((u32)h[3] << 16);
        lw.x = (u32)l[0] | ((u32)l[1] << 16); lw.y = (u32)l[2] | ((u32)l[3] << 16);
        size_t base = ((size_t)b * NSP + n0 + nr) * CDIM + c0 + c4;
        *(uint2*)&d1[base] = hw;
        *(uint2*)&d2[base] = lw;
    }
}

// ---------------------------------------------------------------------------
// Kernel C: proj via mma (3-pass split bf16 core).
// Q: fp16 xLOG2E.  K: fp16.  V: fp16 [c][n] natural.
// ---------------------------------------------------------------------------
#define PJ_X1 0
#define PJ_X2 33792
#define PJ_W  67584
#define PJ_ST 202752
#define PJ_B  220160
#define PJ_TOTAL 221184

__global__ __launch_bounds__(256, 1) void proj_mma(
    const float* __restrict__ bq, const float* __restrict__ bk,
    const float* __restrict__ bv)
{
    extern __shared__ __align__(16) char smem[];
    const u32 sb = smem_u32(smem);
    const int tid = threadIdx.x;
    const int lane = tid & 31, warp = tid >> 5;
    const int wr = warp >> 1, wc = warp & 1;
    const int gid = lane >> 2, tig = lane & 3;
    const int z = blockIdx.z, bb = blockIdx.y, n0 = blockIdx.x * 64;

    const __nv_bfloat16* xs1 = (z == 0) ? g_Xx1 : g_Xa1;
    const __nv_bfloat16* xs2 = (z == 0) ? g_Xx2 : g_Xa2;
    const __nv_bfloat16* w1 = g_W1[z];
    const __nv_bfloat16* w2 = g_W2[z];
    const float* bias = (z == 0) ? bq : (z == 1) ? bk : bv;

    float* bias_s = (float*)(smem + PJ_B);
    bias_s[tid] = bias[tid];

    #pragma unroll
    for (int it = 0; it < 8; it++) {
        int idx = it * 256 + tid;
        int j = idx >> 5, ch = idx & 31;
        size_t off = ((size_t)bb * NSP + n0 + j) * CDIM + ch * 8;
        CP16(sb + PJ_X1 + j * 528 + ch * 16, xs1 + off);
        CP16(sb + PJ_X2 + j * 528 + ch * 16, xs2 + off);
    }
    CPCOMMIT();

    auto issueW = [&](int oq) {
        u32 base = sb + PJ_W + (oq & 1) * 67584;
        #pragma unroll
        for (int it = 0; it < 8; it++) {
            int idx = it * 256 + tid;
            int o = idx >> 5, ch = idx & 31;
            size_t off = (size_t)(oq * 64 + o) * CDIM + ch * 8;
            CP16(base + o * 528 + ch * 16, w1 + off);
            CP16(base + 33792 + o * 528 + ch * 16, w2 + off);
        }
        CPCOMMIT();
    };
    issueW(0);

    const u32 aB1 = sb + PJ_X1 + (wr * 16 + (lane & 15)) * 528 + (lane >> 4) * 16;
    const u32 aB2 = sb + PJ_X2 + (wr * 16 + (lane & 15)) * 528 + (lane >> 4) * 16;
    const int bRow = wc * 32 + (lane & 7) + ((lane >> 4) << 3);
    const u32 bOffc = ((lane >> 3) & 1) * 16;

    for (int oq = 0; oq < 4; oq++) {
        CPWAIT(0);
        __syncthreads();
        if (oq < 3) issueW(oq + 1);

        u32 wbase = sb + PJ_W + (oq & 1) * 67584;
        u32 bB1 = wbase + bRow * 528 + bOffc;
        u32 bB2 = bB1 + 33792;

        float D[4][4];
        #pragma unroll
        for (int t = 0; t < 4; t++)
            #pragma unroll
            for (int e = 0; e < 4; e++) D[t][e] = 0.0f;

        #pragma unroll
        for (int kk = 0; kk < 16; kk++) {
            u32 a1[4], a2[4], bw1[8], bw2[8];
            ldsm4(a1, aB1 + kk * 32);
            ldsm4(a2, aB2 + kk * 32);
            ldsm4(bw1,     bB1 + kk * 32);
            ldsm4(bw1 + 4, bB1 + 16 * 528 + kk * 32);
            ldsm4(bw2,     bB2 + kk * 32);
            ldsm4(bw2 + 4, bB2 + 16 * 528 + kk * 32);
            #pragma unroll
            for (int t = 0; t < 4; t++) {
                mma_bf16(D[t], a1, bw1[2 * t], bw1[2 * t + 1]);
                mma_bf16(D[t], a1, bw2[2 * t], bw2[2 * t + 1]);
                mma_bf16(D[t], a2, bw1[2 * t], bw1[2 * t + 1]);
            }
        }

        if (z < 2) {
            __half* dst = (z == 0) ? g_Qh : g_Kh;
            const float sc = (z == 0) ? LOG2E : 1.0f;
            #pragma unroll
            for (int t = 0; t < 4; t++) {
                int o = oq * 64 + wc * 32 + t * 8 + 2 * tig;
                float b0 = bias_s[o], b1 = bias_s[o + 1];
                #pragma unroll
                for (int rh = 0; rh < 2; rh++) {
                    float f0 = (D[t][2 * rh + 0] + b0) * sc;
                    float f1 = (D[t][2 * rh + 1] + b1) * sc;
                    int n = n0 + wr * 16 + gid + rh * 8;
                    size_t idx = ((size_t)bb * NSP + n) * CDIM + o;
                    *(u32*)&dst[idx] = packh2(f0, f1);
                }
            }
        } else {
            float* st = (float*)(smem + PJ_ST);
            #pragma unroll
            for (int t = 0; t < 4; t++) {
                int ol = wc * 32 + t * 8 + 2 * tig;
                float b0 = bias_s[oq * 64 + ol], b1 = bias_s[oq * 64 + ol + 1];
                #pragma unroll
                for (int rh = 0; rh < 2; rh++) {
                    int nl = wr * 16 + gid + rh * 8;
                    st[ol * 68 + nl]       = D[t][2 * rh + 0] + b0;
                    st[(ol + 1) * 68 + nl] = D[t][2 * rh + 1] + b1;
                }
            }
            __syncthreads();
            // fp16 store, natural order
            int ol = tid >> 2, nch = (tid & 3) * 16;
            u32 hv[8];
            #pragma unroll
            for (int m = 0; m < 8; m++) {
                int s = nch + 2 * m;
                hv[m] = packh2(st[ol * 68 + s], st[ol * 68 + s + 1]);
            }
            __half* dst = g_Vh + ((size_t)bb * CDIM + oq * 64 + ol) * NSP + n0 + nch;
            *(uint4*)&dst[0] = make_uint4(hv[0], hv[1], hv[2], hv[3]);
            *(uint4*)&dst[8] = make_uint4(hv[4], hv[5], hv[6], hv[7]);
        }
    }
}

// ---------------------------------------------------------------------------
// Kernel D: flash attention, 256 threads, BK=32, 2 CTAs/SM, fp16 PV +
// online row-max (P in (0,1] fp16).
// S: wr=warp>>1 (i-slice16), wcs=warp&1 (j-half16).
// PV: wi=warp>>2 (i-half32), wcq=warp&3 (c-quarter64).
// ---------------------------------------------------------------------------
#define SQ   0
#define SK   33792
#define SVH  50688
#define SP   71168        // 64 x 72B fp16 P
#define SMX  75776        // mx[2][64] f32
#define SMP  76288        // m_prev ping-pong [2][64] f32
#define SLR  76800        // lrow 64 f32
#define SM_TOTAL 77056
#define QK_STR 528
#define VH_STR 80
#define P_STR  72
#define OT_STR 258

__global__ __launch_bounds__(256, 2) void attn_kernel(
    const float* __restrict__ x, float* __restrict__ out)
{
    extern __shared__ __align__(16) char smem[];
    const u32 sb = smem_u32(smem);
    const int tid = threadIdx.x;
    const int lane = tid & 31;
    const int warp = tid >> 5;
    const int wr = warp >> 1, wcs = warp & 1;     // S roles
    const int wi = warp >> 2, wcq = warp & 3;     // PV roles
    const int gid = lane >> 2, tig = lane & 3;
    const int i0s = wr * 16, j0s = wcs * 16;
    const int i0p = wi * 32, c0q = wcq * 64;
    const int bb = blockIdx.y;
    const int n0 = blockIdx.x * BQ;

    float* lrow = (float*)(smem + SLR);
    float* mxa  = (float*)(smem + SMX);   // [2][64]
    float* mpp  = (float*)(smem + SMP);   // [2][64]
    if (tid < 64) { lrow[tid] = 0.0f; mpp[tid] = -1e30f; }

    const __half* qg  = g_Qh + ((size_t)bb * NSP + n0) * CDIM;
    const __half* khg = g_Kh + (size_t)bb * NSP * CDIM;
    const __half* vhg = g_Vh + (size_t)bb * CDIM * NSP;

    // ---- Q tile (fp16): 64 rows x 512B ----
    #pragma unroll
    for (int it = 0; it < 8; it++) {
        int idx = it * 256 + tid;
        int i = idx >> 5, ch = idx & 31;
        uint4 v = *(const uint4*)&qg[(size_t)i * CDIM + ch * 8];
        sts_v4(sb + SQ + i * QK_STR + ch * 16, v);
    }

    auto issueK = [&](int k0) {
        #pragma unroll
        for (int it = 0; it < 4; it++) {
            int idx = it * 256 + tid;
            int j = idx >> 5, ch = idx & 31;
            CP16(sb + SK + j * QK_STR + ch * 16, &khg[(size_t)(k0 + j) * CDIM + ch * 8]);
        }
        CPCOMMIT();
    };
    auto issueV = [&](int k0) {
        #pragma unroll
        for (int it = 0; it < 4; it++) {
            int idx = it * 256 + tid;
            int c = idx >> 2, ch = idx & 3;
            CP16(sb + SVH + c * VH_STR + ch * 16, &vhg[(size_t)c * NSP + k0 + ch * 8]);
        }
        CPCOMMIT();
    };

    issueK(0);
    issueV(0);

    const u32 aBase = sb + SQ + (i0s + (lane & 15)) * QK_STR + (lane >> 4) * 16;
    const int bRow = j0s + (lane & 7) + ((lane >> 4) << 3);
    const u32 bBase = sb + SK + bRow * QK_STR + ((lane >> 3) & 1) * 16;

    float O[2][8][4];
    #pragma unroll
    for (int it = 0; it < 2; it++)
        #pragma unroll
        for (int nt = 0; nt < 8; nt++)
            #pragma unroll
            for (int e = 0; e < 4; e++) O[it][nt][e] = 0.0f;
    float lsum0 = 0.0f, lsum1 = 0.0f;

    for (int kt = 0; kt < NK; kt++) {
        CPWAIT(1);                  // K(kt) ready
        __syncthreads();

        // ---- S = q * k : 16i x 16j per warp, fp16 ----
        float S[2][4];
        #pragma unroll
        for (int t = 0; t < 2; t++)
            #pragma unroll
            for (int e = 0; e < 4; e++) S[t][e] = 0.0f;

        #pragma unroll
        for (int kk = 0; kk < 16; kk++) {
            u32 aq[4], bk[4];
            ldsm4(aq, aBase + kk * 32);
            ldsm4(bk, bBase + kk * 32);
            mma_f16(S[0], aq, bk[0], bk[1]);
            mma_f16(S[1], aq, bk[2], bk[3]);
        }

        // ---- warp-half row max -> mx[wcs][row] ----
        {
            float rm0 = fmaxf(fmaxf(S[0][0], S[0][1]), fmaxf(S[1][0], S[1][1]));
            float rm1 = fmaxf(fmaxf(S[0][2], S[0][3]), fmaxf(S[1][2], S[1][3]));
            rm0 = fmaxf(rm0, __shfl_xor_sync(0xffffffffu, rm0, 1));
            rm0 = fmaxf(rm0, __shfl_xor_sync(0xffffffffu, rm0, 2));
            rm1 = fmaxf(rm1, __shfl_xor_sync(0xffffffffu, rm1, 1));
            rm1 = fmaxf(rm1, __shfl_xor_sync(0xffffffffu, rm1, 2));
            if (tig == 0) {
                sts_f32(sb + SMX + (wcs * 64 + i0s + gid) * 4, rm0);
                sts_f32(sb + SMX + (wcs * 64 + i0s + gid + 8) * 4, rm1);
            }
        }

        CPWAIT(0);                  // V(kt) ready; K read done; mx visible
        __syncthreads();
        issueK(((kt + 1) & (NK - 1)) * BK);

        const float* mprev = mpp + (kt & 1) * 64;
        float* mnext = mpp + ((kt & 1) ^ 1) * 64;

        // ---- softmax: m_new, P=exp2(s-m) fp16, lsum rescale ----
        {
            int r0 = i0s + gid, r1 = r0 + 8;
            float mn0 = fmaxf(fmaxf(mxa[r0], mxa[64 + r0]), mprev[r0]);
            float mn1 = fmaxf(fmaxf(mxa[r1], mxa[64 + r1]), mprev[r1]);
            lsum0 *= ex2f(mprev[r0] - mn0);
            lsum1 *= ex2f(mprev[r1] - mn1);
            #pragma unroll
            for (int t = 0; t < 2; t++) {
                int jc = j0s + 8 * t + 2 * tig;
                float p0 = ex2f(S[t][0] - mn0), p1 = ex2f(S[t][1] - mn0);
                float p2 = ex2f(S[t][2] - mn1), p3 = ex2f(S[t][3] - mn1);
                lsum0 += p0 + p1;
                lsum1 += p2 + p3;
                sts_u32(sb + SP + r0 * P_STR + jc * 2, packh2(p0, p1));
                sts_u32(sb + SP + r1 * P_STR + jc * 2, packh2(p2, p3));
            }
            if (wcs == 0 && tig == 0) {
                sts_f32(sb + SMP + (((kt & 1) ^ 1) * 64 + r0) * 4, mn0);
                sts_f32(sb + SMP + (((kt & 1) ^ 1) * 64 + r1) * 4, mn1);
            }
        }

        // ---- O rescale for PV rows (skip when max unchanged) ----
        #pragma unroll
        for (int it = 0; it < 2; it++) {
            int r = i0p + it * 16 + gid;
            float mpa = mprev[r], mpb = mprev[r + 8];
            float mna = fmaxf(fmaxf(mxa[r], mxa[64 + r]), mpa);
            float mnb = fmaxf(fmaxf(mxa[r + 8], mxa[64 + r + 8]), mpb);
            if (mpa < mna || mpb < mnb) {
                float sa = ex2f(mpa - mna), sbf = ex2f(mpb - mnb);
                #pragma unroll
                for (int nt = 0; nt < 8; nt++) {
                    O[it][nt][0] *= sa;  O[it][nt][1] *= sa;
                    O[it][nt][2] *= sbf; O[it][nt][3] *= sbf;
                }
            }
        }
        BAR_GRP(1 + wi);            // P (and mnext) exchange within i-half

        // ---- O += P @ V^T : 32i x 64c per warp, fp16 m16n8k16, k=32 ----
        const u32 pB = sb + SP + (i0p + gid) * P_STR + tig * 4;
        const u32 vB = sb + SVH + (c0q + gid) * VH_STR + tig * 4;
        #pragma unroll
        for (int ks = 0; ks < 2; ks++) {
            u32 a[2][4];
            #pragma unroll
            for (int it = 0; it < 2; it++) {
                u32 pa = pB + it * 16 * P_STR + ks * 32;
                a[it][0] = lds_u32(pa);
                a[it][1] = lds_u32(pa + 8 * P_STR);
                a[it][2] = lds_u32(pa + 16);
                a[it][3] = lds_u32(pa + 8 * P_STR + 16);
            }
            #pragma unroll
            for (int nt = 0; nt < 8; nt++) {
                u32 vb = vB + nt * 8 * VH_STR + ks * 32;
                u32 b0 = lds_u32(vb);
                u32 b1 = lds_u32(vb + 16);
                mma_f16(O[0][nt], a[0], b0, b1);
                mma_f16(O[1][nt], a[1], b0, b1);
            }
        }
        __syncthreads();            // V, P, mx fully read
        if (kt + 1 < NK) issueV((kt + 1) * BK);
    }

    CPWAIT(0);

    // ---- per-row l: quad reduce + atomic over 2 wcs warps ----
    lsum0 += __shfl_xor_sync(0xffffffffu, lsum0, 1);
    lsum0 += __shfl_xor_sync(0xffffffffu, lsum0, 2);
    lsum1 += __shfl_xor_sync(0xffffffffu, lsum1, 1);
    lsum1 += __shfl_xor_sync(0xffffffffu, lsum1, 2);
    if (tig == 0) {
        atomicAdd(&lrow[i0s + gid], lsum0);
        atomicAdd(&lrow[i0s + gid + 8], lsum1);
    }
    __syncthreads();

    // ---- transpose O through smem (reuse SQ/SK region) ----
    #pragma unroll
    for (int it = 0; it < 2; it++)
        #pragma unroll
        for (int nt = 0; nt < 8; nt++) {
            int i = i0p + it * 16 + gid;
            int c = c0q + nt * 8 + 2 * tig;
            sts_v2f(sb + (i * OT_STR + c) * 4, O[it][nt][0], O[it][nt][1]);
            sts_v2f(sb + ((i + 8) * OT_STR + c) * 4, O[it][nt][2], O[it][nt][3]);
        }
    __syncthreads();

    // ---- out = O/l + x, coalesced ----
    const float* xb = x + (size_t)bb * CDIM * NSP;
    float* ob = out + (size_t)bb * CDIM * NSP;
    const int i = tid & 63;
    const int cg = tid >> 6;
    const float invl = 1.0f / lrow[i];
    #pragma unroll 4
    for (int cc = 0; cc < 64; cc++) {
        int c = cc * 4 + cg;
        float ov = lds_f32(sb + (i * OT_STR + c) * 4);
        size_t g = (size_t)c * NSP + n0 + i;
        ob[g] = ov * invl + xb[g];
    }
}

// ---------------------------------------------------------------------------
extern "C" void kernel_launch(void* const* d_in, const int* in_sizes, int n_in,
                              void* d_out, int out_size)
{
    const float* x    = (const float*)d_in[0];
    const float* attr = (const float*)d_in[1];
    const float* Wq   = (const float*)d_in[2];
    const float* bq   = (const float*)d_in[3];
    const float* Wk   = (const float*)d_in[4];
    const float* bk   = (const float*)d_in[5];
    const float* Wv   = (const float*)d_in[6];
    const float* bv   = (const float*)d_in[7];
    float* out = (float*)d_out;

    cudaFuncSetAttribute(proj_mma,
                         cudaFuncAttributeMaxDynamicSharedMemorySize, PJ_TOTAL);
    cudaFuncSetAttribute(attn_kernel,
                         cudaFuncAttributeMaxDynamicSharedMemorySize, SM_TOTAL);

    split_w<<<768, 256>>>(Wq, Wk, Wv);
    split_x<<<dim3(NSP / 32, CDIM / 32, NB * 2), 256>>>(x, attr);
    proj_mma<<<dim3(NSP / 64, NB, 3), 256, PJ_TOTAL>>>(bq, bk, bv);
    attn_kernel<<<dim3(NSP / BQ, NB), 256, SM_TOTAL>>>(x, out);
}

// round 13
// speedup vs baseline: 1.5178x; 1.0580x over previous
#include <cuda_runtime.h>
#include <cuda_bf16.h>
#include <cuda_fp16.h>

#define NSP 4096
#define CDIM 256
#define NB 8
#define BQ 64
#define BK 32
#define NK (NSP / BK)
#define LOG2E 1.4426950408889634f

// ---- scratch ----
__device__ __align__(256) __half g_Qh[(size_t)NB * NSP * CDIM];   // [b][n][c] fp16 (xLOG2E)
__device__ __align__(256) __half g_Kh[(size_t)NB * NSP * CDIM];   // [b][n][c] fp16
__device__ __align__(256) __half g_Vh[(size_t)NB * CDIM * NSP];   // [b][c][n] fp16 natural
__device__ __align__(256) __nv_bfloat16 g_Xx1[(size_t)NB * NSP * CDIM];
__device__ __align__(256) __nv_bfloat16 g_Xx2[(size_t)NB * NSP * CDIM];
__device__ __align__(256) __nv_bfloat16 g_Xa1[(size_t)NB * NSP * CDIM];
__device__ __align__(256) __nv_bfloat16 g_Xa2[(size_t)NB * NSP * CDIM];
__device__ __align__(256) __nv_bfloat16 g_W1[3][65536];
__device__ __align__(256) __nv_bfloat16 g_W2[3][65536];

typedef unsigned long long u64;
typedef unsigned int u32;
typedef unsigned short u16;

// ================= helpers =================
__device__ __forceinline__ u32 smem_u32(const void* p) {
    u32 a;
    asm("{ .reg .u64 t; cvta.to.shared.u64 t, %1; cvt.u32.u64 %0, t; }" : "=r"(a) : "l"(p));
    return a;
}
__device__ __forceinline__ float ex2f(float x) {
    float y; asm("ex2.approx.f32 %0, %1;" : "=f"(y) : "f"(x)); return y;
}
__device__ __forceinline__ void ldsm4(u32* r, u32 addr) {
    asm volatile("ldmatrix.sync.aligned.m8n8.x4.shared.b16 {%0,%1,%2,%3}, [%4];"
                 : "=r"(r[0]), "=r"(r[1]), "=r"(r[2]), "=r"(r[3]) : "r"(addr));
}
__device__ __forceinline__ void mma_bf16(float* d, const u32* a, u32 b0, u32 b1) {
    asm volatile(
        "mma.sync.aligned.m16n8k16.row.col.f32.bf16.bf16.f32 "
        "{%0,%1,%2,%3}, {%4,%5,%6,%7}, {%8,%9}, {%0,%1,%2,%3};"
        : "+f"(d[0]), "+f"(d[1]), "+f"(d[2]), "+f"(d[3])
        : "r"(a[0]), "r"(a[1]), "r"(a[2]), "r"(a[3]), "r"(b0), "r"(b1));
}
__device__ __forceinline__ void mma_f16(float* d, const u32* a, u32 b0, u32 b1) {
    asm volatile(
        "mma.sync.aligned.m16n8k16.row.col.f32.f16.f16.f32 "
        "{%0,%1,%2,%3}, {%4,%5,%6,%7}, {%8,%9}, {%0,%1,%2,%3};"
        : "+f"(d[0]), "+f"(d[1]), "+f"(d[2]), "+f"(d[3])
        : "r"(a[0]), "r"(a[1]), "r"(a[2]), "r"(a[3]), "r"(b0), "r"(b1));
}
__device__ __forceinline__ u32 lds_u32(u32 a) {
    u32 v; asm volatile("ld.shared.b32 %0, [%1];" : "=r"(v) : "r"(a)); return v;
}
__device__ __forceinline__ float lds_f32(u32 a) {
    float v; asm volatile("ld.shared.f32 %0, [%1];" : "=f"(v) : "r"(a)); return v;
}
__device__ __forceinline__ void sts_u32(u32 a, u32 v) {
    asm volatile("st.shared.b32 [%0], %1;" :: "r"(a), "r"(v) : "memory");
}
__device__ __forceinline__ void sts_f32(u32 a, float v) {
    asm volatile("st.shared.f32 [%0], %1;" :: "r"(a), "f"(v) : "memory");
}
__device__ __forceinline__ void sts_v2f(u32 a, float x, float y) {
    asm volatile("st.shared.v2.f32 [%0], {%1,%2};" :: "r"(a), "f"(x), "f"(y) : "memory");
}
__device__ __forceinline__ void sts_v4(u32 a, uint4 v) {
    asm volatile("st.shared.v4.b32 [%0], {%1,%2,%3,%4};"
                 :: "r"(a), "r"(v.x), "r"(v.y), "r"(v.z), "r"(v.w) : "memory");
}
#define CP16(dst, src) asm volatile("cp.async.cg.shared.global [%0], [%1], 16;" \
    :: "r"(dst), "l"(src) : "memory")
#define CPCOMMIT() asm volatile("cp.async.commit_group;" ::: "memory")
#define CPWAIT(n)  asm volatile("cp.async.wait_group %0;" :: "n"(n) : "memory")
#define BAR_GRP(id) asm volatile("bar.sync %0, %1;" :: "r"(id), "r"(128) : "memory")

__device__ __forceinline__ void bfsplit(float f, u16& hi, u16& lo) {
    __nv_bfloat16 h = __float2bfloat16_rn(f);
    __nv_bfloat16 l = __float2bfloat16_rn(f - __bfloat162float(h));
    hi = __bfloat16_as_ushort(h);
    lo = __bfloat16_as_ushort(l);
}
__device__ __forceinline__ u32 packh2(float a, float b) {
    __half h0 = __float2half_rn(a);
    __half h1 = __float2half_rn(b);
    return (u32)__half_as_ushort(h0) | ((u32)__half_as_ushort(h1) << 16);
}

// ---------------------------------------------------------------------------
// Kernel A: split weights into bf16 hi/lo pairs.
// ---------------------------------------------------------------------------
__global__ __launch_bounds__(256) void split_w(
    const float* __restrict__ Wq, const float* __restrict__ Wk,
    const float* __restrict__ Wv)
{
    int idx = blockIdx.x * 256 + threadIdx.x;
    int which = idx >> 16;
    int i = idx & 65535;
    const float* W = (which == 0) ? Wq : (which == 1) ? Wk : Wv;
    u16 h, l;
    bfsplit(W[i], h, l);
    g_W1[which][i] = __ushort_as_bfloat16(h);
    g_W2[which][i] = __ushort_as_bfloat16(l);
}

// ---------------------------------------------------------------------------
// Kernel B: split + transpose x/attr -> [b][n][c] bf16 hi/lo.
// ---------------------------------------------------------------------------
__global__ __launch_bounds__(256) void split_x(
    const float* __restrict__ x, const float* __restrict__ attr)
{
    __shared__ float t[32][33];
    const int tid = threadIdx.x;
    const int b = blockIdx.z >> 1, ten = blockIdx.z & 1;
    const float* src = ten ? attr : x;
    __nv_bfloat16* d1 = ten ? g_Xa1 : g_Xx1;
    __nv_bfloat16* d2 = ten ? g_Xa2 : g_Xx2;
    const int n0 = blockIdx.x * 32, c0 = blockIdx.y * 32;

    {
        int r = tid >> 3, n4 = (tid & 7) * 4;
        float4 v = *(const float4*)(src + ((size_t)b * CDIM + c0 + r) * NSP + n0 + n4);
        t[r][n4 + 0] = v.x; t[r][n4 + 1] = v.y;
        t[r][n4 + 2] = v.z; t[r][n4 + 3] = v.w;
    }
    __syncthreads();
    {
        int nr = tid >> 3, c4 = (tid & 7) * 4;
        u16 h[4], l[4];
        #pragma unroll
        for (int k = 0; k < 4; k++) bfsplit(t[c4 + k][nr], h[k], l[k]);
        uint2 hw, lw;
        hw.x = (u32)h[0] | ((u32)h[1] << 16); hw.y = (u32)h[2] | ((u32)h[3] << 16);
        lw.x = (u32)l[0] | ((u32)l[1] << 16); lw.y = (u32)l[2] | ((u32)l[3] << 16);
        size_t base = ((size_t)b * NSP + n0 + nr) * CDIM + c0 + c4;
        *(uint2*)&d1[base] = hw;
        *(uint2*)&d2[base] = lw;
    }
}

// ---------------------------------------------------------------------------
// Kernel C: proj via mma (3-pass split bf16 core).
// Q: fp16 xLOG2E.  K: fp16.  V: fp16 [c][n] natural.
// ---------------------------------------------------------------------------
#define PJ_X1 0
#define PJ_X2 33792
#define PJ_W  67584
#define PJ_ST 202752
#define PJ_B  220160
#define PJ_TOTAL 221184

__global__ __launch_bounds__(256, 1) void proj_mma(
    const float* __restrict__ bq, const float* __restrict__ bk,
    const float* __restrict__ bv)
{
    extern __shared__ __align__(16) char smem[];
    const u32 sb = smem_u32(smem);
    const int tid = threadIdx.x;
    const int lane = tid & 31, warp = tid >> 5;
    const int wr = warp >> 1, wc = warp & 1;
    const int gid = lane >> 2, tig = lane & 3;
    const int z = blockIdx.z, bb = blockIdx.y, n0 = blockIdx.x * 64;

    const __nv_bfloat16* xs1 = (z == 0) ? g_Xx1 : g_Xa1;
    const __nv_bfloat16* xs2 = (z == 0) ? g_Xx2 : g_Xa2;
    const __nv_bfloat16* w1 = g_W1[z];
    const __nv_bfloat16* w2 = g_W2[z];
    const float* bias = (z == 0) ? bq : (z == 1) ? bk : bv;

    float* bias_s = (float*)(smem + PJ_B);
    bias_s[tid] = bias[tid];

    #pragma unroll
    for (int it = 0; it < 8; it++) {
        int idx = it * 256 + tid;
        int j = idx >> 5, ch = idx & 31;
        size_t off = ((size_t)bb * NSP + n0 + j) * CDIM + ch * 8;
        CP16(sb + PJ_X1 + j * 528 + ch * 16, xs1 + off);
        CP16(sb + PJ_X2 + j * 528 + ch * 16, xs2 + off);
    }
    CPCOMMIT();

    auto issueW = [&](int oq) {
        u32 base = sb + PJ_W + (oq & 1) * 67584;
        #pragma unroll
        for (int it = 0; it < 8; it++) {
            int idx = it * 256 + tid;
            int o = idx >> 5, ch = idx & 31;
            size_t off = (size_t)(oq * 64 + o) * CDIM + ch * 8;
            CP16(base + o * 528 + ch * 16, w1 + off);
            CP16(base + 33792 + o * 528 + ch * 16, w2 + off);
        }
        CPCOMMIT();
    };
    issueW(0);

    const u32 aB1 = sb + PJ_X1 + (wr * 16 + (lane & 15)) * 528 + (lane >> 4) * 16;
    const u32 aB2 = sb + PJ_X2 + (wr * 16 + (lane & 15)) * 528 + (lane >> 4) * 16;
    const int bRow = wc * 32 + (lane & 7) + ((lane >> 4) << 3);
    const u32 bOffc = ((lane >> 3) & 1) * 16;

    for (int oq = 0; oq < 4; oq++) {
        CPWAIT(0);
        __syncthreads();
        if (oq < 3) issueW(oq + 1);

        u32 wbase = sb + PJ_W + (oq & 1) * 67584;
        u32 bB1 = wbase + bRow * 528 + bOffc;
        u32 bB2 = bB1 + 33792;

        float D[4][4];
        #pragma unroll
        for (int t = 0; t < 4; t++)
            #pragma unroll
            for (int e = 0; e < 4; e++) D[t][e] = 0.0f;

        #pragma unroll
        for (int kk = 0; kk < 16; kk++) {
            u32 a1[4], a2[4], bw1[8], bw2[8];
            ldsm4(a1, aB1 + kk * 32);
            ldsm4(a2, aB2 + kk * 32);
            ldsm4(bw1,     bB1 + kk * 32);
            ldsm4(bw1 + 4, bB1 + 16 * 528 + kk * 32);
            ldsm4(bw2,     bB2 + kk * 32);
            ldsm4(bw2 + 4, bB2 + 16 * 528 + kk * 32);
            #pragma unroll
            for (int t = 0; t < 4; t++) {
                mma_bf16(D[t], a1, bw1[2 * t], bw1[2 * t + 1]);
                mma_bf16(D[t], a1, bw2[2 * t], bw2[2 * t + 1]);
                mma_bf16(D[t], a2, bw1[2 * t], bw1[2 * t + 1]);
            }
        }

        if (z < 2) {
            __half* dst = (z == 0) ? g_Qh : g_Kh;
            const float sc = (z == 0) ? LOG2E : 1.0f;
            #pragma unroll
            for (int t = 0; t < 4; t++) {
                int o = oq * 64 + wc * 32 + t * 8 + 2 * tig;
                float b0 = bias_s[o], b1 = bias_s[o + 1];
                #pragma unroll
                for (int rh = 0; rh < 2; rh++) {
                    float f0 = (D[t][2 * rh + 0] + b0) * sc;
                    float f1 = (D[t][2 * rh + 1] + b1) * sc;
                    int n = n0 + wr * 16 + gid + rh * 8;
                    size_t idx = ((size_t)bb * NSP + n) * CDIM + o;
                    *(u32*)&dst[idx] = packh2(f0, f1);
                }
            }
        } else {
            float* st = (float*)(smem + PJ_ST);
            #pragma unroll
            for (int t = 0; t < 4; t++) {
                int ol = wc * 32 + t * 8 + 2 * tig;
                float b0 = bias_s[oq * 64 + ol], b1 = bias_s[oq * 64 + ol + 1];
                #pragma unroll
                for (int rh = 0; rh < 2; rh++) {
                    int nl = wr * 16 + gid + rh * 8;
                    st[ol * 68 + nl]       = D[t][2 * rh + 0] + b0;
                    st[(ol + 1) * 68 + nl] = D[t][2 * rh + 1] + b1;
                }
            }
            __syncthreads();
            int ol = tid >> 2, nch = (tid & 3) * 16;
            u32 hv[8];
            #pragma unroll
            for (int m = 0; m < 8; m++) {
                int s = nch + 2 * m;
                hv[m] = packh2(st[ol * 68 + s], st[ol * 68 + s + 1]);
            }
            __half* dst = g_Vh + ((size_t)bb * CDIM + oq * 64 + ol) * NSP + n0 + nch;
            *(uint4*)&dst[0] = make_uint4(hv[0], hv[1], hv[2], hv[3]);
            *(uint4*)&dst[8] = make_uint4(hv[4], hv[5], hv[6], hv[7]);
        }
    }
}

// ---------------------------------------------------------------------------
// Kernel D: flash attention, 256 threads, BK=32, 2 CTAs/SM, fp16 PV with
// ldmatrix-fragged P and V, online row-max.
// ---------------------------------------------------------------------------
#define SQ   0
#define SK   33792
#define SVH  50688        // 256 x 80B fp16 V
#define SP   71168        // 64 x 80B fp16 P
#define SMX  76288        // mx[2][64] f32
#define SMP  76800        // m_prev ping-pong [2][64] f32
#define SLR  77312        // lrow 64 f32
#define SM_TOTAL 77568
#define QK_STR 528
#define VH_STR 80
#define P_STR  80
#define OT_STR 258

__global__ __launch_bounds__(256, 2) void attn_kernel(
    const float* __restrict__ x, float* __restrict__ out)
{
    extern __shared__ __align__(16) char smem[];
    const u32 sb = smem_u32(smem);
    const int tid = threadIdx.x;
    const int lane = tid & 31;
    const int warp = tid >> 5;
    const int wr = warp >> 1, wcs = warp & 1;     // S roles
    const int wi = warp >> 2, wcq = warp & 3;     // PV roles
    const int gid = lane >> 2, tig = lane & 3;
    const int i0s = wr * 16, j0s = wcs * 16;
    const int i0p = wi * 32, c0q = wcq * 64;
    const int bb = blockIdx.y;
    const int n0 = blockIdx.x * BQ;

    float* lrow = (float*)(smem + SLR);
    float* mxa  = (float*)(smem + SMX);   // [2][64]
    float* mpp  = (float*)(smem + SMP);   // [2][64]
    if (tid < 64) { lrow[tid] = 0.0f; mpp[tid] = -1e30f; }

    const __half* qg  = g_Qh + ((size_t)bb * NSP + n0) * CDIM;
    const __half* khg = g_Kh + (size_t)bb * NSP * CDIM;
    const __half* vhg = g_Vh + (size_t)bb * CDIM * NSP;

    // ---- Q tile (fp16): 64 rows x 512B ----
    #pragma unroll
    for (int it = 0; it < 8; it++) {
        int idx = it * 256 + tid;
        int i = idx >> 5, ch = idx & 31;
        uint4 v = *(const uint4*)&qg[(size_t)i * CDIM + ch * 8];
        sts_v4(sb + SQ + i * QK_STR + ch * 16, v);
    }

    auto issueK = [&](int k0) {
        #pragma unroll
        for (int it = 0; it < 4; it++) {
            int idx = it * 256 + tid;
            int j = idx >> 5, ch = idx & 31;
            CP16(sb + SK + j * QK_STR + ch * 16, &khg[(size_t)(k0 + j) * CDIM + ch * 8]);
        }
        CPCOMMIT();
    };
    auto issueV = [&](int k0) {
        #pragma unroll
        for (int it = 0; it < 4; it++) {
            int idx = it * 256 + tid;
            int c = idx >> 2, ch = idx & 3;
            CP16(sb + SVH + c * VH_STR + ch * 16, &vhg[(size_t)c * NSP + k0 + ch * 8]);
        }
        CPCOMMIT();
    };

    issueK(0);
    issueV(0);

    const u32 aBase = sb + SQ + (i0s + (lane & 15)) * QK_STR + (lane >> 4) * 16;
    const int bRow = j0s + (lane & 7) + ((lane >> 4) << 3);
    const u32 bBase = sb + SK + bRow * QK_STR + ((lane >> 3) & 1) * 16;
    // PV ldsm bases
    const u32 pldB = sb + SP + (i0p + (lane & 15)) * P_STR + (lane >> 4) * 16;
    const u32 vldB = sb + SVH + (c0q + (lane & 7) + ((lane >> 4) << 3)) * VH_STR
                   + ((lane >> 3) & 1) * 16;

    float O[2][8][4];
    #pragma unroll
    for (int it = 0; it < 2; it++)
        #pragma unroll
        for (int nt = 0; nt < 8; nt++)
            #pragma unroll
            for (int e = 0; e < 4; e++) O[it][nt][e] = 0.0f;
    float lsum0 = 0.0f, lsum1 = 0.0f;

    for (int kt = 0; kt < NK; kt++) {
        CPWAIT(1);                  // K(kt) ready
        __syncthreads();

        // ---- S = q * k : 16i x 16j per warp, fp16 ----
        float S[2][4];
        #pragma unroll
        for (int t = 0; t < 2; t++)
            #pragma unroll
            for (int e = 0; e < 4; e++) S[t][e] = 0.0f;

        #pragma unroll
        for (int kk = 0; kk < 16; kk++) {
            u32 aq[4], bk[4];
            ldsm4(aq, aBase + kk * 32);
            ldsm4(bk, bBase + kk * 32);
            mma_f16(S[0], aq, bk[0], bk[1]);
            mma_f16(S[1], aq, bk[2], bk[3]);
        }

        // ---- warp-half row max -> mx[wcs][row] ----
        {
            float rm0 = fmaxf(fmaxf(S[0][0], S[0][1]), fmaxf(S[1][0], S[1][1]));
            float rm1 = fmaxf(fmaxf(S[0][2], S[0][3]), fmaxf(S[1][2], S[1][3]));
            rm0 = fmaxf(rm0, __shfl_xor_sync(0xffffffffu, rm0, 1));
            rm0 = fmaxf(rm0, __shfl_xor_sync(0xffffffffu, rm0, 2));
            rm1 = fmaxf(rm1, __shfl_xor_sync(0xffffffffu, rm1, 1));
            rm1 = fmaxf(rm1, __shfl_xor_sync(0xffffffffu, rm1, 2));
            if (tig == 0) {
                sts_f32(sb + SMX + (wcs * 64 + i0s + gid) * 4, rm0);
                sts_f32(sb + SMX + (wcs * 64 + i0s + gid + 8) * 4, rm1);
            }
        }

        CPWAIT(0);                  // V(kt) ready; K read done; mx visible
        __syncthreads();
        issueK(((kt + 1) & (NK - 1)) * BK);

        const float* mprev = mpp + (kt & 1) * 64;

        // ---- softmax: m_new, P=exp2(s-m) fp16, lsum rescale ----
        {
            int r0 = i0s + gid, r1 = r0 + 8;
            float mn0 = fmaxf(fmaxf(mxa[r0], mxa[64 + r0]), mprev[r0]);
            float mn1 = fmaxf(fmaxf(mxa[r1], mxa[64 + r1]), mprev[r1]);
            lsum0 *= ex2f(mprev[r0] - mn0);
            lsum1 *= ex2f(mprev[r1] - mn1);
            #pragma unroll
            for (int t = 0; t < 2; t++) {
                int jc = j0s + 8 * t + 2 * tig;
                float p0 = ex2f(S[t][0] - mn0), p1 = ex2f(S[t][1] - mn0);
                float p2 = ex2f(S[t][2] - mn1), p3 = ex2f(S[t][3] - mn1);
                lsum0 += p0 + p1;
                lsum1 += p2 + p3;
                sts_u32(sb + SP + r0 * P_STR + jc * 2, packh2(p0, p1));
                sts_u32(sb + SP + r1 * P_STR + jc * 2, packh2(p2, p3));
            }
            if (wcs == 0 && tig == 0) {
                sts_f32(sb + SMP + (((kt & 1) ^ 1) * 64 + r0) * 4, mn0);
                sts_f32(sb + SMP + (((kt & 1) ^ 1) * 64 + r1) * 4, mn1);
            }
        }

        // ---- O rescale for PV rows (skip when max unchanged) ----
        #pragma unroll
        for (int it = 0; it < 2; it++) {
            int r = i0p + it * 16 + gid;
            float mpa = mprev[r], mpb = mprev[r + 8];
            float mna = fmaxf(fmaxf(mxa[r], mxa[64 + r]), mpa);
            float mnb = fmaxf(fmaxf(mxa[r + 8], mxa[64 + r + 8]), mpb);
            if (mpa < mna || mpb < mnb) {
                float sa = ex2f(mpa - mna), sbf = ex2f(mpb - mnb);
                #pragma unroll
                for (int nt = 0; nt < 8; nt++) {
                    O[it][nt][0] *= sa;  O[it][nt][1] *= sa;
                    O[it][nt][2] *= sbf; O[it][nt][3] *= sbf;
                }
            }
        }
        BAR_GRP(1 + wi);            // P exchange within i-half

        // ---- O += P @ V^T : 32i x 64c per warp, fp16, ldsm frags ----
        #pragma unroll
        for (int ks = 0; ks < 2; ks++) {
            u32 a0[4], a1[4];
            ldsm4(a0, pldB + ks * 32);
            ldsm4(a1, pldB + 16 * P_STR + ks * 32);
            #pragma unroll
            for (int m = 0; m < 4; m++) {
                u32 vb[4];
                ldsm4(vb, vldB + m * 16 * VH_STR + ks * 32);
                mma_f16(O[0][2 * m],     a0, vb[0], vb[1]);
                mma_f16(O[0][2 * m + 1], a0, vb[2], vb[3]);
                mma_f16(O[1][2 * m],     a1, vb[0], vb[1]);
                mma_f16(O[1][2 * m + 1], a1, vb[2], vb[3]);
            }
        }
        __syncthreads();            // V, P, mx fully read
        if (kt + 1 < NK) issueV((kt + 1) * BK);
    }

    CPWAIT(0);

    // ---- per-row l: quad reduce + atomic over 2 wcs warps ----
    lsum0 += __shfl_xor_sync(0xffffffffu, lsum0, 1);
    lsum0 += __shfl_xor_sync(0xffffffffu, lsum0, 2);
    lsum1 += __shfl_xor_sync(0xffffffffu, lsum1, 1);
    lsum1 += __shfl_xor_sync(0xffffffffu, lsum1, 2);
    if (tig == 0) {
        atomicAdd(&lrow[i0s + gid], lsum0);
        atomicAdd(&lrow[i0s + gid + 8], lsum1);
    }
    __syncthreads();

    // ---- transpose O through smem (reuse SQ/SK region) ----
    #pragma unroll
    for (int it = 0; it < 2; it++)
        #pragma unroll
        for (int nt = 0; nt < 8; nt++) {
            int i = i0p + it * 16 + gid;
            int c = c0q + nt * 8 + 2 * tig;
            sts_v2f(sb + (i * OT_STR + c) * 4, O[it][nt][0], O[it][nt][1]);
            sts_v2f(sb + ((i + 8) * OT_STR + c) * 4, O[it][nt][2], O[it][nt][3]);
        }
    __syncthreads();

    // ---- out = O/l + x, coalesced ----
    const float* xb = x + (size_t)bb * CDIM * NSP;
    float* ob = out + (size_t)bb * CDIM * NSP;
    const int i = tid & 63;
    const int cg = tid >> 6;
    const float invl = 1.0f / lrow[i];
    #pragma unroll 4
    for (int cc = 0; cc < 64; cc++) {
        int c = cc * 4 + cg;
        float ov = lds_f32(sb + (i * OT_STR + c) * 4);
        size_t g = (size_t)c * NSP + n0 + i;
        ob[g] = ov * invl + xb[g];
    }
}

// ---------------------------------------------------------------------------
extern "C" void kernel_launch(void* const* d_in, const int* in_sizes, int n_in,
                              void* d_out, int out_size)
{
    const float* x    = (const float*)d_in[0];
    const float* attr = (const float*)d_in[1];
    const float* Wq   = (const float*)d_in[2];
    const float* bq   = (const float*)d_in[3];
    const float* Wk   = (const float*)d_in[4];
    const float* bk   = (const float*)d_in[5];
    const float* Wv   = (const float*)d_in[6];
    const float* bv   = (const float*)d_in[7];
    float* out = (float*)d_out;

    cudaFuncSetAttribute(proj_mma,
                         cudaFuncAttributeMaxDynamicSharedMemorySize, PJ_TOTAL);
    cudaFuncSetAttribute(attn_kernel,
                         cudaFuncAttributeMaxDynamicSharedMemorySize, SM_TOTAL);

    split_w<<<768, 256>>>(Wq, Wk, Wv);
    split_x<<<dim3(NSP / 32, CDIM / 32, NB * 2), 256>>>(x, attr);
    proj_mma<<<dim3(NSP / 64, NB, 3), 256, PJ_TOTAL>>>(bq, bk, bv);
    attn_kernel<<<dim3(NSP / BQ, NB), 256, SM_TOTAL>>>(x, out);
}

// round 14
// speedup vs baseline: 1.5298x; 1.0079x over previous
#include <cuda_runtime.h>
#include <cuda_bf16.h>
#include <cuda_fp16.h>

#define NSP 4096
#define CDIM 256
#define NB 8
#define BQ 64
#define BK 32
#define NK (NSP / BK)
#define LOG2E 1.4426950408889634f

// ---- scratch ----
__device__ __align__(256) __half g_Qh[(size_t)NB * NSP * CDIM];   // [b][n][c] fp16 (xLOG2E)
__device__ __align__(256) __half g_Kh[(size_t)NB * NSP * CDIM];   // [b][n][c] fp16
__device__ __align__(256) __half g_Vh[(size_t)NB * CDIM * NSP];   // [b][c][n] fp16 natural
__device__ __align__(256) __nv_bfloat16 g_Xx1[(size_t)NB * NSP * CDIM];
__device__ __align__(256) __nv_bfloat16 g_Xx2[(size_t)NB * NSP * CDIM];
__device__ __align__(256) __nv_bfloat16 g_Xa1[(size_t)NB * NSP * CDIM];
__device__ __align__(256) __nv_bfloat16 g_Xa2[(size_t)NB * NSP * CDIM];
__device__ __align__(256) __nv_bfloat16 g_W1[3][65536];
__device__ __align__(256) __nv_bfloat16 g_W2[3][65536];

typedef unsigned long long u64;
typedef unsigned int u32;
typedef unsigned short u16;

// ================= helpers =================
__device__ __forceinline__ u32 smem_u32(const void* p) {
    u32 a;
    asm("{ .reg .u64 t; cvta.to.shared.u64 t, %1; cvt.u32.u64 %0, t; }" : "=r"(a) : "l"(p));
    return a;
}
__device__ __forceinline__ float ex2f(float x) {
    float y; asm("ex2.approx.f32 %0, %1;" : "=f"(y) : "f"(x)); return y;
}
__device__ __forceinline__ void ldsm4(u32* r, u32 addr) {
    asm volatile("ldmatrix.sync.aligned.m8n8.x4.shared.b16 {%0,%1,%2,%3}, [%4];"
                 : "=r"(r[0]), "=r"(r[1]), "=r"(r[2]), "=r"(r[3]) : "r"(addr));
}
__device__ __forceinline__ void mma_bf16(float* d, const u32* a, u32 b0, u32 b1) {
    asm volatile(
        "mma.sync.aligned.m16n8k16.row.col.f32.bf16.bf16.f32 "
        "{%0,%1,%2,%3}, {%4,%5,%6,%7}, {%8,%9}, {%0,%1,%2,%3};"
        : "+f"(d[0]), "+f"(d[1]), "+f"(d[2]), "+f"(d[3])
        : "r"(a[0]), "r"(a[1]), "r"(a[2]), "r"(a[3]), "r"(b0), "r"(b1));
}
__device__ __forceinline__ void mma_f16(float* d, const u32* a, u32 b0, u32 b1) {
    asm volatile(
        "mma.sync.aligned.m16n8k16.row.col.f32.f16.f16.f32 "
        "{%0,%1,%2,%3}, {%4,%5,%6,%7}, {%8,%9}, {%0,%1,%2,%3};"
        : "+f"(d[0]), "+f"(d[1]), "+f"(d[2]), "+f"(d[3])
        : "r"(a[0]), "r"(a[1]), "r"(a[2]), "r"(a[3]), "r"(b0), "r"(b1));
}
__device__ __forceinline__ u32 lds_u32(u32 a) {
    u32 v; asm volatile("ld.shared.b32 %0, [%1];" : "=r"(v) : "r"(a)); return v;
}
__device__ __forceinline__ float lds_f32(u32 a) {
    float v; asm volatile("ld.shared.f32 %0, [%1];" : "=f"(v) : "r"(a)); return v;
}
__device__ __forceinline__ void sts_u32(u32 a, u32 v) {
    asm volatile("st.shared.b32 [%0], %1;" :: "r"(a), "r"(v) : "memory");
}
__device__ __forceinline__ void sts_f32(u32 a, float v) {
    asm volatile("st.shared.f32 [%0], %1;" :: "r"(a), "f"(v) : "memory");
}
__device__ __forceinline__ void sts_v2f(u32 a, float x, float y) {
    asm volatile("st.shared.v2.f32 [%0], {%1,%2};" :: "r"(a), "f"(x), "f"(y) : "memory");
}
__device__ __forceinline__ void sts_v4(u32 a, uint4 v) {
    asm volatile("st.shared.v4.b32 [%0], {%1,%2,%3,%4};"
                 :: "r"(a), "r"(v.x), "r"(v.y), "r"(v.z), "r"(v.w) : "memory");
}
#define CP16(dst, src) asm volatile("cp.async.cg.shared.global [%0], [%1], 16;" \
    :: "r"(dst), "l"(src) : "memory")
#define CPCOMMIT() asm volatile("cp.async.commit_group;" ::: "memory")
#define CPWAIT(n)  asm volatile("cp.async.wait_group %0;" :: "n"(n) : "memory")
#define BAR_GRP(id) asm volatile("bar.sync %0, %1;" :: "r"(id), "r"(128) : "memory")

__device__ __forceinline__ void bfsplit(float f, u16& hi, u16& lo) {
    __nv_bfloat16 h = __float2bfloat16_rn(f);
    __nv_bfloat16 l = __float2bfloat16_rn(f - __bfloat162float(h));
    hi = __bfloat16_as_ushort(h);
    lo = __bfloat16_as_ushort(l);
}
__device__ __forceinline__ u32 packh2(float a, float b) {
    __half h0 = __float2half_rn(a);
    __half h1 = __float2half_rn(b);
    return (u32)__half_as_ushort(h0) | ((u32)__half_as_ushort(h1) << 16);
}

// ---------------------------------------------------------------------------
// Kernel A: split weights into bf16 hi/lo pairs.
// ---------------------------------------------------------------------------
__global__ __launch_bounds__(256) void split_w(
    const float* __restrict__ Wq, const float* __restrict__ Wk,
    const float* __restrict__ Wv)
{
    int idx = blockIdx.x * 256 + threadIdx.x;
    int which = idx >> 16;
    int i = idx & 65535;
    const float* W = (which == 0) ? Wq : (which == 1) ? Wk : Wv;
    u16 h, l;
    bfsplit(W[i], h, l);
    g_W1[which][i] = __ushort_as_bfloat16(h);
    g_W2[which][i] = __ushort_as_bfloat16(l);
}

// ---------------------------------------------------------------------------
// Kernel B: split + transpose x/attr -> [b][n][c] bf16 hi/lo.
// ---------------------------------------------------------------------------
__global__ __launch_bounds__(256) void split_x(
    const float* __restrict__ x, const float* __restrict__ attr)
{
    __shared__ float t[32][33];
    const int tid = threadIdx.x;
    const int b = blockIdx.z >> 1, ten = blockIdx.z & 1;
    const float* src = ten ? attr : x;
    __nv_bfloat16* d1 = ten ? g_Xa1 : g_Xx1;
    __nv_bfloat16* d2 = ten ? g_Xa2 : g_Xx2;
    const int n0 = blockIdx.x * 32, c0 = blockIdx.y * 32;

    {
        int r = tid >> 3, n4 = (tid & 7) * 4;
        float4 v = *(const float4*)(src + ((size_t)b * CDIM + c0 + r) * NSP + n0 + n4);
        t[r][n4 + 0] = v.x; t[r][n4 + 1] = v.y;
        t[r][n4 + 2] = v.z; t[r][n4 + 3] = v.w;
    }
    __syncthreads();
    {
        int nr = tid >> 3, c4 = (tid & 7) * 4;
        u16 h[4], l[4];
        #pragma unroll
        for (int k = 0; k < 4; k++) bfsplit(t[c4 + k][nr], h[k], l[k]);
        uint2 hw, lw;
        hw.x = (u32)h[0] | ((u32)h[1] << 16); hw.y = (u32)h[2] | ((u32)h[3] << 16);
        lw.x = (u32)l[0] | ((u32)l[1] << 16); lw.y = (u32)l[2] | ((u32)l[3] << 16);
        size_t base = ((size_t)b * NSP + n0 + nr) * CDIM + c0 + c4;
        *(uint2*)&d1[base] = hw;
        *(uint2*)&d2[base] = lw;
    }
}

// ---------------------------------------------------------------------------
// Kernel C: proj via mma (3-pass split bf16 core).  (unchanged)
// ---------------------------------------------------------------------------
#define PJ_X1 0
#define PJ_X2 33792
#define PJ_W  67584
#define PJ_ST 202752
#define PJ_B  220160
#define PJ_TOTAL 221184

__global__ __launch_bounds__(256, 1) void proj_mma(
    const float* __restrict__ bq, const float* __restrict__ bk,
    const float* __restrict__ bv)
{
    extern __shared__ __align__(16) char smem[];
    const u32 sb = smem_u32(smem);
    const int tid = threadIdx.x;
    const int lane = tid & 31, warp = tid >> 5;
    const int wr = warp >> 1, wc = warp & 1;
    const int gid = lane >> 2, tig = lane & 3;
    const int z = blockIdx.z, bb = blockIdx.y, n0 = blockIdx.x * 64;

    const __nv_bfloat16* xs1 = (z == 0) ? g_Xx1 : g_Xa1;
    const __nv_bfloat16* xs2 = (z == 0) ? g_Xx2 : g_Xa2;
    const __nv_bfloat16* w1 = g_W1[z];
    const __nv_bfloat16* w2 = g_W2[z];
    const float* bias = (z == 0) ? bq : (z == 1) ? bk : bv;

    float* bias_s = (float*)(smem + PJ_B);
    bias_s[tid] = bias[tid];

    #pragma unroll
    for (int it = 0; it < 8; it++) {
        int idx = it * 256 + tid;
        int j = idx >> 5, ch = idx & 31;
        size_t off = ((size_t)bb * NSP + n0 + j) * CDIM + ch * 8;
        CP16(sb + PJ_X1 + j * 528 + ch * 16, xs1 + off);
        CP16(sb + PJ_X2 + j * 528 + ch * 16, xs2 + off);
    }
    CPCOMMIT();

    auto issueW = [&](int oq) {
        u32 base = sb + PJ_W + (oq & 1) * 67584;
        #pragma unroll
        for (int it = 0; it < 8; it++) {
            int idx = it * 256 + tid;
            int o = idx >> 5, ch = idx & 31;
            size_t off = (size_t)(oq * 64 + o) * CDIM + ch * 8;
            CP16(base + o * 528 + ch * 16, w1 + off);
            CP16(base + 33792 + o * 528 + ch * 16, w2 + off);
        }
        CPCOMMIT();
    };
    issueW(0);

    const u32 aB1 = sb + PJ_X1 + (wr * 16 + (lane & 15)) * 528 + (lane >> 4) * 16;
    const u32 aB2 = sb + PJ_X2 + (wr * 16 + (lane & 15)) * 528 + (lane >> 4) * 16;
    const int bRow = wc * 32 + (lane & 7) + ((lane >> 4) << 3);
    const u32 bOffc = ((lane >> 3) & 1) * 16;

    for (int oq = 0; oq < 4; oq++) {
        CPWAIT(0);
        __syncthreads();
        if (oq < 3) issueW(oq + 1);

        u32 wbase = sb + PJ_W + (oq & 1) * 67584;
        u32 bB1 = wbase + bRow * 528 + bOffc;
        u32 bB2 = bB1 + 33792;

        float D[4][4];
        #pragma unroll
        for (int t = 0; t < 4; t++)
            #pragma unroll
            for (int e = 0; e < 4; e++) D[t][e] = 0.0f;

        #pragma unroll
        for (int kk = 0; kk < 16; kk++) {
            u32 a1[4], a2[4], bw1[8], bw2[8];
            ldsm4(a1, aB1 + kk * 32);
            ldsm4(a2, aB2 + kk * 32);
            ldsm4(bw1,     bB1 + kk * 32);
            ldsm4(bw1 + 4, bB1 + 16 * 528 + kk * 32);
            ldsm4(bw2,     bB2 + kk * 32);
            ldsm4(bw2 + 4, bB2 + 16 * 528 + kk * 32);
            #pragma unroll
            for (int t = 0; t < 4; t++) {
                mma_bf16(D[t], a1, bw1[2 * t], bw1[2 * t + 1]);
                mma_bf16(D[t], a1, bw2[2 * t], bw2[2 * t + 1]);
                mma_bf16(D[t], a2, bw1[2 * t], bw1[2 * t + 1]);
            }
        }

        if (z < 2) {
            __half* dst = (z == 0) ? g_Qh : g_Kh;
            const float sc = (z == 0) ? LOG2E : 1.0f;
            #pragma unroll
            for (int t = 0; t < 4; t++) {
                int o = oq * 64 + wc * 32 + t * 8 + 2 * tig;
                float b0 = bias_s[o], b1 = bias_s[o + 1];
                #pragma unroll
                for (int rh = 0; rh < 2; rh++) {
                    float f0 = (D[t][2 * rh + 0] + b0) * sc;
                    float f1 = (D[t][2 * rh + 1] + b1) * sc;
                    int n = n0 + wr * 16 + gid + rh * 8;
                    size_t idx = ((size_t)bb * NSP + n) * CDIM + o;
                    *(u32*)&dst[idx] = packh2(f0, f1);
                }
            }
        } else {
            float* st = (float*)(smem + PJ_ST);
            #pragma unroll
            for (int t = 0; t < 4; t++) {
                int ol = wc * 32 + t * 8 + 2 * tig;
                float b0 = bias_s[oq * 64 + ol], b1 = bias_s[oq * 64 + ol + 1];
                #pragma unroll
                for (int rh = 0; rh < 2; rh++) {
                    int nl = wr * 16 + gid + rh * 8;
                    st[ol * 68 + nl]       = D[t][2 * rh + 0] + b0;
                    st[(ol + 1) * 68 + nl] = D[t][2 * rh + 1] + b1;
                }
            }
            __syncthreads();
            int ol = tid >> 2, nch = (tid & 3) * 16;
            u32 hv[8];
            #pragma unroll
            for (int m = 0; m < 8; m++) {
                int s = nch + 2 * m;
                hv[m] = packh2(st[ol * 68 + s], st[ol * 68 + s + 1]);
            }
            __half* dst = g_Vh + ((size_t)bb * CDIM + oq * 64 + ol) * NSP + n0 + nch;
            *(uint4*)&dst[0] = make_uint4(hv[0], hv[1], hv[2], hv[3]);
            *(uint4*)&dst[8] = make_uint4(hv[4], hv[5], hv[6], hv[7]);
        }
    }
}

// ---------------------------------------------------------------------------
// Kernel D: flash attention, software-pipelined: S(kt) interleaved with
// PV(kt-1).  256 threads, BK=32, 2 CTAs/SM, fp16 throughout, online max.
// ---------------------------------------------------------------------------
#define SQ    0
#define SK    33792
#define SV0   50688       // 256 x 80B fp16 V, double buffered
#define SVSZ  20480
#define SP0   91648       // 64 x 80B fp16 P, double buffered
#define SPSZ  5120
#define SMX   101888      // mx[2][64] f32
#define SMP   102400      // m_prev ping-pong [2][64] f32
#define SLR   102912      // lrow 64 f32
#define SM_TOTAL 103168
#define QK_STR 528
#define VH_STR 80
#define P_STR  80
#define OT_STR 258

__global__ __launch_bounds__(256, 2) void attn_kernel(
    const float* __restrict__ x, float* __restrict__ out)
{
    extern __shared__ __align__(16) char smem[];
    const u32 sb = smem_u32(smem);
    const int tid = threadIdx.x;
    const int lane = tid & 31;
    const int warp = tid >> 5;
    const int wr = warp >> 1, wcs = warp & 1;     // S roles
    const int wi = warp >> 2;                     // PV i-half
    const int wcq = warp & 3;                     // PV c-quarter
    const int gid = lane >> 2, tig = lane & 3;
    const int i0s = wr * 16, j0s = wcs * 16;
    const int i0p = wi * 32, c0q = wcq * 64;
    const int bb = blockIdx.y;
    const int n0 = blockIdx.x * BQ;

    float* lrow = (float*)(smem + SLR);
    float* mxa  = (float*)(smem + SMX);
    if (tid < 64) {
        lrow[tid] = 0.0f;
        ((float*)(smem + SMP))[tid] = -1e30f;
    }

    const __half* qg  = g_Qh + ((size_t)bb * NSP + n0) * CDIM;
    const __half* khg = g_Kh + (size_t)bb * NSP * CDIM;
    const __half* vhg = g_Vh + (size_t)bb * CDIM * NSP;

    // ---- Q tile ----
    #pragma unroll
    for (int it = 0; it < 8; it++) {
        int idx = it * 256 + tid;
        int i = idx >> 5, ch = idx & 31;
        uint4 v = *(const uint4*)&qg[(size_t)i * CDIM + ch * 8];
        sts_v4(sb + SQ + i * QK_STR + ch * 16, v);
    }

    auto issueK = [&](int k0) {
        #pragma unroll
        for (int it = 0; it < 4; it++) {
            int idx = it * 256 + tid;
            int j = idx >> 5, ch = idx & 31;
            CP16(sb + SK + j * QK_STR + ch * 16, &khg[(size_t)(k0 + j) * CDIM + ch * 8]);
        }
        CPCOMMIT();
    };
    auto issueV = [&](int kt) {
        u32 base = sb + SV0 + (kt & 1) * SVSZ;
        int k0 = kt * BK;
        #pragma unroll
        for (int it = 0; it < 4; it++) {
            int idx = it * 256 + tid;
            int c = idx >> 2, ch = idx & 3;
            CP16(base + c * VH_STR + ch * 16, &vhg[(size_t)c * NSP + k0 + ch * 8]);
        }
        CPCOMMIT();
    };

    issueK(0);
    issueV(0);

    const u32 aBase = sb + SQ + (i0s + (lane & 15)) * QK_STR + (lane >> 4) * 16;
    const int bRow = j0s + (lane & 7) + ((lane >> 4) << 3);
    const u32 bBase = sb + SK + bRow * QK_STR + ((lane >> 3) & 1) * 16;
    const u32 pldB = sb + SP0 + (i0p + (lane & 15)) * P_STR + (lane >> 4) * 16;
    const u32 vldB = sb + SV0 + (c0q + (lane & 7) + ((lane >> 4) << 3)) * VH_STR
                   + ((lane >> 3) & 1) * 16;

    float O[2][8][4];
    #pragma unroll
    for (int it = 0; it < 2; it++)
        #pragma unroll
        for (int nt = 0; nt < 8; nt++)
            #pragma unroll
            for (int e = 0; e < 4; e++) O[it][nt][e] = 0.0f;
    float lsum0 = 0.0f, lsum1 = 0.0f;

    // ======== epilogue-of-tile helper (max store, softmax, rescale) ========
    auto tile_tail = [&](int kt, float S[2][4]) {
        // warp-half row max -> mx[wcs][row]
        float rm0 = fmaxf(fmaxf(S[0][0], S[0][1]), fmaxf(S[1][0], S[1][1]));
        float rm1 = fmaxf(fmaxf(S[0][2], S[0][3]), fmaxf(S[1][2], S[1][3]));
        rm0 = fmaxf(rm0, __shfl_xor_sync(0xffffffffu, rm0, 1));
        rm0 = fmaxf(rm0, __shfl_xor_sync(0xffffffffu, rm0, 2));
        rm1 = fmaxf(rm1, __shfl_xor_sync(0xffffffffu, rm1, 1));
        rm1 = fmaxf(rm1, __shfl_xor_sync(0xffffffffu, rm1, 2));
        if (tig == 0) {
            sts_f32(sb + SMX + (wcs * 64 + i0s + gid) * 4, rm0);
            sts_f32(sb + SMX + (wcs * 64 + i0s + gid + 8) * 4, rm1);
        }
        __syncthreads();            // mx visible; K/V reads of this phase done
        issueK(((kt + 1) & (NK - 1)) * BK);
        if (kt + 1 < NK) issueV(kt + 1);

        const float* mprev = (float*)(smem + SMP) + (kt & 1) * 64;
        // softmax: P(kt) fp16
        {
            int r0 = i0s + gid, r1 = r0 + 8;
            float mn0 = fmaxf(fmaxf(mxa[r0], mxa[64 + r0]), mprev[r0]);
            float mn1 = fmaxf(fmaxf(mxa[r1], mxa[64 + r1]), mprev[r1]);
            lsum0 *= ex2f(mprev[r0] - mn0);
            lsum1 *= ex2f(mprev[r1] - mn1);
            u32 pbase = sb + SP0 + (kt & 1) * SPSZ;
            #pragma unroll
            for (int t = 0; t < 2; t++) {
                int jc = j0s + 8 * t + 2 * tig;
                float p0 = ex2f(S[t][0] - mn0), p1 = ex2f(S[t][1] - mn0);
                float p2 = ex2f(S[t][2] - mn1), p3 = ex2f(S[t][3] - mn1);
                lsum0 += p0 + p1;
                lsum1 += p2 + p3;
                sts_u32(pbase + r0 * P_STR + jc * 2, packh2(p0, p1));
                sts_u32(pbase + r1 * P_STR + jc * 2, packh2(p2, p3));
            }
            if (wcs == 0 && tig == 0) {
                sts_f32(sb + SMP + (((kt & 1) ^ 1) * 64 + r0) * 4, mn0);
                sts_f32(sb + SMP + (((kt & 1) ^ 1) * 64 + r1) * 4, mn1);
            }
        }
        // O rescale to m(kt) (PV rows), skip if unchanged
        #pragma unroll
        for (int it = 0; it < 2; it++) {
            int r = i0p + it * 16 + gid;
            float mpa = mprev[r], mpb = mprev[r + 8];
            float mna = fmaxf(fmaxf(mxa[r], mxa[64 + r]), mpa);
            float mnb = fmaxf(fmaxf(mxa[r + 8], mxa[64 + r + 8]), mpb);
            if (mpa < mna || mpb < mnb) {
                float sa = ex2f(mpa - mna), sbf = ex2f(mpb - mnb);
                #pragma unroll
                for (int nt = 0; nt < 8; nt++) {
                    O[it][nt][0] *= sa;  O[it][nt][1] *= sa;
                    O[it][nt][2] *= sbf; O[it][nt][3] *= sbf;
                }
            }
        }
        BAR_GRP(1 + wi);            // P(kt) exchange within i-half
    };

    // ======== tile 0 (no PV yet) ========
    {
        CPWAIT(0);
        __syncthreads();
        float S[2][4];
        #pragma unroll
        for (int t = 0; t < 2; t++)
            #pragma unroll
            for (int e = 0; e < 4; e++) S[t][e] = 0.0f;
        #pragma unroll
        for (int kk = 0; kk < 16; kk++) {
            u32 aq[4], bk[4];
            ldsm4(aq, aBase + kk * 32);
            ldsm4(bk, bBase + kk * 32);
            mma_f16(S[0], aq, bk[0], bk[1]);
            mma_f16(S[1], aq, bk[2], bk[3]);
        }
        tile_tail(0, S);
    }

    // ======== pipelined main loop: S(kt) + PV(kt-1) ========
    for (int kt = 1; kt < NK; kt++) {
        CPWAIT(1);                  // K(kt), V(kt-1) ready (V(kt) pending)
        __syncthreads();

        const u32 pld = pldB + ((kt - 1) & 1) * SPSZ;
        const u32 vld = vldB + ((kt - 1) & 1) * SVSZ;

        float S[2][4];
        #pragma unroll
        for (int t = 0; t < 2; t++)
            #pragma unroll
            for (int e = 0; e < 4; e++) S[t][e] = 0.0f;

        u32 aP0[4], aP1[4];
        #pragma unroll
        for (int kk = 0; kk < 16; kk++) {
            u32 aq[4], bk[4];
            ldsm4(aq, aBase + kk * 32);
            ldsm4(bk, bBase + kk * 32);
            mma_f16(S[0], aq, bk[0], bk[1]);
            mma_f16(S[1], aq, bk[2], bk[3]);
            if ((kk & 1) == 0) {
                int ks = kk >> 3;
                int m = (kk >> 1) & 3;
                if (m == 0) {
                    ldsm4(aP0, pld + ks * 32);
                    ldsm4(aP1, pld + 16 * P_STR + ks * 32);
                }
                u32 vb[4];
                ldsm4(vb, vld + m * 16 * VH_STR + ks * 32);
                mma_f16(O[0][2 * m],     aP0, vb[0], vb[1]);
                mma_f16(O[0][2 * m + 1], aP0, vb[2], vb[3]);
                mma_f16(O[1][2 * m],     aP1, vb[0], vb[1]);
                mma_f16(O[1][2 * m + 1], aP1, vb[2], vb[3]);
            }
        }
        tile_tail(kt, S);
    }

    // ======== final PV(NK-1) ========
    CPWAIT(0);
    __syncthreads();
    {
        const u32 pld = pldB + ((NK - 1) & 1) * SPSZ;
        const u32 vld = vldB + ((NK - 1) & 1) * SVSZ;
        #pragma unroll
        for (int ks = 0; ks < 2; ks++) {
            u32 a0[4], a1[4];
            ldsm4(a0, pld + ks * 32);
            ldsm4(a1, pld + 16 * P_STR + ks * 32);
            #pragma unroll
            for (int m = 0; m < 4; m++) {
                u32 vb[4];
                ldsm4(vb, vld + m * 16 * VH_STR + ks * 32);
                mma_f16(O[0][2 * m],     a0, vb[0], vb[1]);
                mma_f16(O[0][2 * m + 1], a0, vb[2], vb[3]);
                mma_f16(O[1][2 * m],     a1, vb[0], vb[1]);
                mma_f16(O[1][2 * m + 1], a1, vb[2], vb[3]);
            }
        }
    }

    // ---- per-row l reduce ----
    lsum0 += __shfl_xor_sync(0xffffffffu, lsum0, 1);
    lsum0 += __shfl_xor_sync(0xffffffffu, lsum0, 2);
    lsum1 += __shfl_xor_sync(0xffffffffu, lsum1, 1);
    lsum1 += __shfl_xor_sync(0xffffffffu, lsum1, 2);
    if (tig == 0) {
        atomicAdd(&lrow[i0s + gid], lsum0);
        atomicAdd(&lrow[i0s + gid + 8], lsum1);
    }
    __syncthreads();

    // ---- transpose O through smem ----
    #pragma unroll
    for (int it = 0; it < 2; it++)
        #pragma unroll
        for (int nt = 0; nt < 8; nt++) {
            int i = i0p + it * 16 + gid;
            int c = c0q + nt * 8 + 2 * tig;
            sts_v2f(sb + (i * OT_STR + c) * 4, O[it][nt][0], O[it][nt][1]);
            sts_v2f(sb + ((i + 8) * OT_STR + c) * 4, O[it][nt][2], O[it][nt][3]);
        }
    __syncthreads();

    // ---- out = O/l + x ----
    const float* xb = x + (size_t)bb * CDIM * NSP;
    float* ob = out + (size_t)bb * CDIM * NSP;
    const int i = tid & 63;
    const int cg = tid >> 6;
    const float invl = 1.0f / lrow[i];
    #pragma unroll 4
    for (int cc = 0; cc < 64; cc++) {
        int c = cc * 4 + cg;
        float ov = lds_f32(sb + (i * OT_STR + c) * 4);
        size_t g = (size_t)c * NSP + n0 + i;
        ob[g] = ov * invl + xb[g];
    }
}

// ---------------------------------------------------------------------------
extern "C" void kernel_launch(void* const* d_in, const int* in_sizes, int n_in,
                              void* d_out, int out_size)
{
    const float* x    = (const float*)d_in[0];
    const float* attr = (const float*)d_in[1];
    const float* Wq   = (const float*)d_in[2];
    const float* bq   = (const float*)d_in[3];
    const float* Wk   = (const float*)d_in[4];
    const float* bk   = (const float*)d_in[5];
    const float* Wv   = (const float*)d_in[6];
    const float* bv   = (const float*)d_in[7];
    float* out = (float*)d_out;

    cudaFuncSetAttribute(proj_mma,
                         cudaFuncAttributeMaxDynamicSharedMemorySize, PJ_TOTAL);
    cudaFuncSetAttribute(attn_kernel,
                         cudaFuncAttributeMaxDynamicSharedMemorySize, SM_TOTAL);

    split_w<<<768, 256>>>(Wq, Wk, Wv);
    split_x<<<dim3(NSP / 32, CDIM / 32, NB * 2), 256>>>(x, attr);
    proj_mma<<<dim3(NSP / 64, NB, 3), 256, PJ_TOTAL>>>(bq, bk, bv);
    attn_kernel<<<dim3(NSP / BQ, NB), 256, SM_TOTAL>>>(x, out);
}